// round 12
// baseline (speedup 1.0000x reference)
#include <cuda_runtime.h>
#include <cuda_fp16.h>
#include <math.h>
#include <stdint.h>

#define B_   2
#define S_   2048
#define H_   2048
#define NH_  16
#define NKV_ 4
#define HD_  128
#define I_   8192
#define NTOK (B_*S_)
#define EPSF 1e-6f

// ---------------------------------------------------------------------------
__device__ float  g_q [NTOK * NH_ * HD_];
__device__ float  g_k [NTOK * NKV_ * HD_];
__device__ float  g_v [NTOK * NKV_ * HD_];
__device__ float  g_x [NTOK * H_];
__device__ float  g_g [NTOK * I_];
__device__ float  g_rope[S_ * HD_];
__device__ __half g_hh [NTOK * H_];
__device__ __half g_oh [NTOK * NH_ * HD_];
__device__ __half g_gh [NTOK * I_];
__device__ __half g_wqT[2048 * 2048];
__device__ __half g_wkT[512 * 2048];
__device__ __half g_wvT[512 * 2048];
__device__ __half g_woT[2048 * 2048];
__device__ __half g_wgT[8192 * 2048];
__device__ __half g_wuT[8192 * 2048];
__device__ __half g_wdT[2048 * 8192];

// ---------------------------------------------------------------------------
__device__ __forceinline__ void mma_f16(float* c, const unsigned* a, const unsigned* b) {
    asm volatile(
        "mma.sync.aligned.m16n8k16.row.col.f32.f16.f16.f32 "
        "{%0,%1,%2,%3},{%4,%5,%6,%7},{%8,%9},{%0,%1,%2,%3};\n"
        : "+f"(c[0]), "+f"(c[1]), "+f"(c[2]), "+f"(c[3])
        : "r"(a[0]), "r"(a[1]), "r"(a[2]), "r"(a[3]), "r"(b[0]), "r"(b[1]));
}

__device__ __forceinline__ void ldsm4(unsigned* r, unsigned addr) {
    asm volatile("ldmatrix.sync.aligned.m8n8.x4.shared.b16 {%0,%1,%2,%3}, [%4];"
        : "=r"(r[0]), "=r"(r[1]), "=r"(r[2]), "=r"(r[3]) : "r"(addr));
}

__device__ __forceinline__ unsigned h2u(__half2 h) {
    return *(unsigned*)&h;
}

__device__ __forceinline__ unsigned smem_u32(const void* p) {
    return (unsigned)__cvta_generic_to_shared(p);
}

#define CP_ASYNC16(dst, src) \
    asm volatile("cp.async.ca.shared.global [%0], [%1], 16;" :: "r"(dst), "l"(src))
#define CP_COMMIT() asm volatile("cp.async.commit_group;" ::: "memory")
#define CP_WAIT(n)  asm volatile("cp.async.wait_group %0;" :: "n"(n) : "memory")

// ---------------------------------------------------------------------------
__global__ void rope_table_kernel() {
    int idx = blockIdx.x * blockDim.x + threadIdx.x;
    if (idx >= S_ * 64) return;
    int pos = idx >> 6;
    int i   = idx & 63;
    float invf = 1.0f / powf(10000.0f, (float)i / 64.0f);
    float ang  = (float)pos * invf;
    g_rope[pos * HD_ + i]      = cosf(ang);
    g_rope[pos * HD_ + 64 + i] = sinf(ang);
}

// ---------------------------------------------------------------------------
__global__ __launch_bounds__(256) void transpose_cvt_kernel(
    const float* __restrict__ W, __half* __restrict__ Wt, int K, int N)
{
    __shared__ float t[32][33];
    int k0 = blockIdx.x * 32, n0 = blockIdx.y * 32;
    int tx = threadIdx.x, ty = threadIdx.y;
#pragma unroll
    for (int j = ty; j < 32; j += 8)
        t[j][tx] = W[(size_t)(k0 + j) * N + n0 + tx];
    __syncthreads();
    if (tx < 16) {
#pragma unroll
        for (int j = ty; j < 32; j += 8) {
            __half2 hv = __floats2half2_rn(t[2 * tx][j], t[2 * tx + 1][j]);
            *(__half2*)(Wt + (size_t)(n0 + j) * K + k0 + 2 * tx) = hv;
        }
    }
}

// ---------------------------------------------------------------------------
__global__ __launch_bounds__(256) void rmsnorm_kernel(
    const float* __restrict__ x, const float* __restrict__ w,
    __half* __restrict__ out)
{
    int row = blockIdx.x;
    const float* xr = x + (size_t)row * H_;
    float ss = 0.f;
#pragma unroll
    for (int it = 0; it < H_ / (256 * 4); it++) {
        int c = (it * 256 + threadIdx.x) * 4;
        float4 t = *(const float4*)(xr + c);
        ss += t.x * t.x + t.y * t.y + t.z * t.z + t.w * t.w;
    }
#pragma unroll
    for (int o = 16; o; o >>= 1) ss += __shfl_xor_sync(0xffffffffu, ss, o);
    __shared__ float red[8];
    if ((threadIdx.x & 31) == 0) red[threadIdx.x >> 5] = ss;
    __syncthreads();
    float tot = 0.f;
#pragma unroll
    for (int i = 0; i < 8; i++) tot += red[i];
    float inv = rsqrtf(tot * (1.0f / H_) + EPSF);
    __half* orow = out + (size_t)row * H_;
#pragma unroll
    for (int it = 0; it < H_ / (256 * 4); it++) {
        int c = (it * 256 + threadIdx.x) * 4;
        float4 t  = *(const float4*)(xr + c);
        float4 wv = *(const float4*)(w + c);
        __half2 h0 = __floats2half2_rn(wv.x * t.x * inv, wv.y * t.y * inv);
        __half2 h1 = __floats2half2_rn(wv.z * t.z * inv, wv.w * t.w * inv);
        *(__half2*)(orow + c)     = h0;
        *(__half2*)(orow + c + 2) = h1;
    }
}

// ---------------------------------------------------------------------------
// FP16 GEMM: cp.async 3-stage (one barrier per k-tile), ldmatrix, 2 CTAs/SM.
// mode 0: C fp32 (+optional addend). mode 1: C = half(silu(addend)*acc).
// ---------------------------------------------------------------------------
#define HSTR 72
#define HBUF (128 * HSTR)
#define NSTG 3
#define HG_SMEM (2 * NSTG * HBUF * 2)

__global__ __launch_bounds__(256, 2) void gemm_h_kernel(
    const __half* __restrict__ A, const __half* __restrict__ Bt,
    const __half* __restrict__ Bt2, const float* __restrict__ addend,
    float* __restrict__ C, float* __restrict__ C2,
    int M, int N, int K, int mode)
{
    extern __shared__ __half smh[];
    if (blockIdx.z == 1) { Bt = Bt2; C = C2; }

    int tid = threadIdx.x;
    int bm = blockIdx.y * 128, bn = blockIdx.x * 128;
    int wid = tid >> 5, lane = tid & 31;
    int wm = (wid & 1) * 64;
    int wn = (wid >> 1) * 32;
    int grp = lane >> 2, qk = lane & 3;

    int lrow = tid >> 3;
    int lseg = (tid & 7) * 8;

    const __half* Ag = A  + (size_t)(bm + lrow) * K + lseg;
    const __half* Bg = Bt + (size_t)(bn + lrow) * K + lseg;

    unsigned sa[NSTG], sb[NSTG];
#pragma unroll
    for (int st = 0; st < NSTG; st++) {
        sa[st] = smem_u32(smh + (2 * st)     * HBUF + lrow * HSTR + lseg);
        sb[st] = smem_u32(smh + (2 * st + 1) * HBUF + lrow * HSTR + lseg);
    }
    const unsigned rowstep = 32 * HSTR * 2;

    // ldmatrix per-lane addresses
    int mi = lane >> 3, lr = lane & 7;
    int miL = mi & 1, miH = mi >> 1;
    unsigned aAdr[NSTG][4], bAdr[NSTG][2];
#pragma unroll
    for (int st = 0; st < NSTG; st++) {
        unsigned ab = smem_u32(smh + (2 * st) * HBUF);
        unsigned bb = smem_u32(smh + (2 * st + 1) * HBUF);
#pragma unroll
        for (int mt = 0; mt < 4; mt++) {
            int rowA = wm + mt * 16 + miL * 8 + lr;
            aAdr[st][mt] = ab + rowA * 144 + miH * 16;
        }
#pragma unroll
        for (int p = 0; p < 2; p++) {
            int rowB = wn + p * 16 + miH * 8 + lr;
            bAdr[st][p] = bb + rowB * 144 + miL * 16;
        }
    }

    float acc[4][4][4];
#pragma unroll
    for (int mt = 0; mt < 4; mt++)
#pragma unroll
        for (int nt = 0; nt < 4; nt++)
#pragma unroll
            for (int r = 0; r < 4; r++) acc[mt][nt][r] = 0.f;

    int nk = K / 64;

    // prologue: issue stages 0 and 1
#pragma unroll
    for (int st = 0; st < 2; st++) {
        const __half* Ag2 = Ag + (size_t)st * 64;
        const __half* Bg2 = Bg + (size_t)st * 64;
#pragma unroll
        for (int s = 0; s < 4; s++) {
            CP_ASYNC16(sa[st] + s * rowstep, Ag2 + (size_t)(32 * s) * K);
            CP_ASYNC16(sb[st] + s * rowstep, Bg2 + (size_t)(32 * s) * K);
        }
        CP_COMMIT();
    }

    for (int kt = 0; kt < nk; kt++) {
        int cur = kt % NSTG;
        if (kt == nk - 1) { CP_WAIT(0); } else { CP_WAIT(1); }
        __syncthreads();

        if (kt + 2 < nk) {
            int nx = (kt + 2) % NSTG;
            const __half* Ag2 = Ag + (size_t)(kt + 2) * 64;
            const __half* Bg2 = Bg + (size_t)(kt + 2) * 64;
#pragma unroll
            for (int s = 0; s < 4; s++) {
                CP_ASYNC16(sa[nx] + s * rowstep, Ag2 + (size_t)(32 * s) * K);
                CP_ASYNC16(sb[nx] + s * rowstep, Bg2 + (size_t)(32 * s) * K);
            }
            CP_COMMIT();
        }

#pragma unroll
        for (int ks = 0; ks < 4; ks++) {
            unsigned koff = ks * 32;
            unsigned afr[4][4], bfr[4][2], bt0[4], bt1[4];
#pragma unroll
            for (int mt = 0; mt < 4; mt++)
                ldsm4(afr[mt], aAdr[cur][mt] + koff);
            ldsm4(bt0, bAdr[cur][0] + koff);
            ldsm4(bt1, bAdr[cur][1] + koff);
            bfr[0][0] = bt0[0]; bfr[0][1] = bt0[1];
            bfr[1][0] = bt0[2]; bfr[1][1] = bt0[3];
            bfr[2][0] = bt1[0]; bfr[2][1] = bt1[1];
            bfr[3][0] = bt1[2]; bfr[3][1] = bt1[3];
#pragma unroll
            for (int mt = 0; mt < 4; mt++)
#pragma unroll
                for (int nt = 0; nt < 4; nt++)
                    mma_f16(acc[mt][nt], afr[mt], bfr[nt]);
        }
    }

    if (mode == 0) {
#pragma unroll
        for (int mt = 0; mt < 4; mt++) {
#pragma unroll
            for (int nt = 0; nt < 4; nt++) {
                int row0 = bm + wm + mt * 16 + grp;
                int col  = bn + wn + nt * 8 + qk * 2;
                float* c0 = C + (size_t)row0 * N + col;
                float* c1 = C + (size_t)(row0 + 8) * N + col;
                if (addend) {
                    const float* a0 = addend + (size_t)row0 * N + col;
                    const float* a1 = addend + (size_t)(row0 + 8) * N + col;
                    *(float2*)c0 = make_float2(acc[mt][nt][0] + a0[0], acc[mt][nt][1] + a0[1]);
                    *(float2*)c1 = make_float2(acc[mt][nt][2] + a1[0], acc[mt][nt][3] + a1[1]);
                } else {
                    *(float2*)c0 = make_float2(acc[mt][nt][0], acc[mt][nt][1]);
                    *(float2*)c1 = make_float2(acc[mt][nt][2], acc[mt][nt][3]);
                }
            }
        }
    } else {
        // swiglu fusion: out_h = silu(g) * u   (g = addend, u = acc)
        __half* Ch = (__half*)C;
#pragma unroll
        for (int mt = 0; mt < 4; mt++) {
#pragma unroll
            for (int nt = 0; nt < 4; nt++) {
                int row0 = bm + wm + mt * 16 + grp;
                int col  = bn + wn + nt * 8 + qk * 2;
                const float* a0 = addend + (size_t)row0 * N + col;
                const float* a1 = addend + (size_t)(row0 + 8) * N + col;
                float g0 = a0[0], g1 = a0[1], g2 = a1[0], g3 = a1[1];
                float r0 = g0 / (1.f + __expf(-g0)) * acc[mt][nt][0];
                float r1 = g1 / (1.f + __expf(-g1)) * acc[mt][nt][1];
                float r2 = g2 / (1.f + __expf(-g2)) * acc[mt][nt][2];
                float r3 = g3 / (1.f + __expf(-g3)) * acc[mt][nt][3];
                *(__half2*)(Ch + (size_t)row0 * N + col)       = __floats2half2_rn(r0, r1);
                *(__half2*)(Ch + (size_t)(row0 + 8) * N + col) = __floats2half2_rn(r2, r3);
            }
        }
    }
}

// ---------------------------------------------------------------------------
__global__ __launch_bounds__(128) void rope_norm_kernel(
    float* __restrict__ qkp, const float* __restrict__ w, int nheads)
{
    int tok  = blockIdx.x;
    int warp = threadIdx.x >> 5;
    int lane = threadIdx.x & 31;
    int head = blockIdx.y * 4 + warp;
    int pos  = tok % S_;

    float* base = qkp + ((size_t)tok * nheads + head) * HD_;
    float a0 = base[lane];      float a1 = base[lane + 32];
    float b0 = base[lane + 64]; float b1 = base[lane + 96];

    const float* rc = g_rope + (size_t)pos * HD_;
    float c0 = rc[lane],      s0 = rc[64 + lane];
    float c1 = rc[lane + 32], s1 = rc[96 + lane];

    float r0  = a0 * c0 - b0 * s0;
    float r64 = b0 * c0 + a0 * s0;
    float r32 = a1 * c1 - b1 * s1;
    float r96 = b1 * c1 + a1 * s1;

    float ss = r0 * r0 + r32 * r32 + r64 * r64 + r96 * r96;
#pragma unroll
    for (int o = 16; o; o >>= 1) ss += __shfl_xor_sync(0xffffffffu, ss, o);
    float inv = rsqrtf(ss * (1.0f / HD_) + EPSF);

    base[lane]      = w[lane]      * r0  * inv;
    base[lane + 32] = w[lane + 32] * r32 * inv;
    base[lane + 64] = w[lane + 64] * r64 * inv;
    base[lane + 96] = w[lane + 96] * r96 * inv;
}

// ---------------------------------------------------------------------------
// FP16 flash attention with ldmatrix fragment feeds. BQ=128, BK=64.
// ---------------------------------------------------------------------------
#define FBQ 128
#define FBK 64
#define QKW 68
#define VTW 36
#define PW  36
#define QS_WORDS (FBQ * QKW)
#define KS_WORDS (FBK * QKW)
#define VT_WORDS (HD_ * VTW)
#define PS_WORDS (FBQ * PW)
#define FLASH_SMEM ((QS_WORDS + KS_WORDS + VT_WORDS + PS_WORDS) * 4)

__global__ __launch_bounds__(256, 2) void flash_kernel(
    const float* __restrict__ q, const float* __restrict__ k,
    const float* __restrict__ v, __half* __restrict__ o)
{
    extern __shared__ unsigned smw[];
    unsigned* Qw = smw;
    unsigned* Kw = Qw + QS_WORDS;
    unsigned* Vw = Kw + KS_WORDS;
    unsigned* Pw = Vw + VT_WORDS;

    int qb = gridDim.x - 1 - blockIdx.x;
    int bh = blockIdx.y;
    int b  = bh / NH_, h = bh % NH_;
    int kvh = h / (NH_ / NKV_);

    int tid = threadIdx.x;
    int wid = tid >> 5, lane = tid & 31;
    int wm = wid * 16;
    int grp = lane >> 2, qk = lane & 3;

    const float scale = 0.08838834764831845f;

    int mi = lane >> 3, lr = lane & 7;
    int miL = mi & 1, miH = mi >> 1;
    unsigned qAdr, pAdr, kAdr[4], vAdr[8];
    {
        int rowQ = wm + miL * 8 + lr;
        qAdr = smem_u32(Qw) + rowQ * 272 + miH * 16;
        int rowP = wm + miL * 8 + lr;
        pAdr = smem_u32(Pw) + rowP * 144 + miH * 16;
#pragma unroll
        for (int p = 0; p < 4; p++) {
            int rowK = p * 16 + miH * 8 + lr;
            kAdr[p] = smem_u32(Kw) + rowK * 272 + miL * 16;
        }
#pragma unroll
        for (int p = 0; p < 8; p++) {
            int rowV = p * 16 + miH * 8 + lr;
            vAdr[p] = smem_u32(Vw) + rowV * 144 + miL * 16;
        }
    }

    const float* qbase = q + ((size_t)(b * S_ + qb * FBQ) * NH_ + h) * HD_;
    for (int i = tid; i < FBQ * (HD_ / 4); i += 256) {
        int r  = i >> 5;
        int c4 = (i & 31) * 4;
        float4 t = *(const float4*)(qbase + (size_t)r * NH_ * HD_ + c4);
        unsigned* dst = Qw + r * QKW + (c4 >> 1);
        dst[0] = h2u(__floats2half2_rn(t.x * scale, t.y * scale));
        dst[1] = h2u(__floats2half2_rn(t.z * scale, t.w * scale));
    }

    float m0 = -1e30f, m1 = -1e30f, l0 = 0.f, l1 = 0.f;
    float oacc[16][4];
#pragma unroll
    for (int nt = 0; nt < 16; nt++)
#pragma unroll
        for (int r = 0; r < 4; r++) oacc[nt][r] = 0.f;

    int nkb = 2 * qb + 2;
    for (int kb = 0; kb < nkb; kb++) {
        __syncthreads();
        const float* kbase = k + ((size_t)(b * S_ + kb * FBK) * NKV_ + kvh) * HD_;
        const float* vbase = v + ((size_t)(b * S_ + kb * FBK) * NKV_ + kvh) * HD_;
        for (int i = tid; i < FBK * (HD_ / 4); i += 256) {
            int r  = i >> 5;
            int c4 = (i & 31) * 4;
            float4 tk = *(const float4*)(kbase + (size_t)r * NKV_ * HD_ + c4);
            unsigned* kd = Kw + r * QKW + (c4 >> 1);
            kd[0] = h2u(__floats2half2_rn(tk.x, tk.y));
            kd[1] = h2u(__floats2half2_rn(tk.z, tk.w));
        }
        for (int i = tid; i < 32 * 32; i += 256) {
            int sp = i & 31;
            int c4 = (i >> 5) * 4;
            float4 va = *(const float4*)(vbase + (size_t)(2 * sp)     * NKV_ * HD_ + c4);
            float4 vb = *(const float4*)(vbase + (size_t)(2 * sp + 1) * NKV_ * HD_ + c4);
            Vw[(c4 + 0) * VTW + sp] = h2u(__floats2half2_rn(va.x, vb.x));
            Vw[(c4 + 1) * VTW + sp] = h2u(__floats2half2_rn(va.y, vb.y));
            Vw[(c4 + 2) * VTW + sp] = h2u(__floats2half2_rn(va.z, vb.z));
            Vw[(c4 + 3) * VTW + sp] = h2u(__floats2half2_rn(va.w, vb.w));
        }
        __syncthreads();

        float s[8][4];
#pragma unroll
        for (int nt = 0; nt < 8; nt++)
#pragma unroll
            for (int r = 0; r < 4; r++) s[nt][r] = 0.f;

#pragma unroll
        for (int ks = 0; ks < 8; ks++) {
            unsigned koff = ks * 32;
            unsigned a[4];
            ldsm4(a, qAdr + koff);
#pragma unroll
            for (int p = 0; p < 4; p++) {
                unsigned bt[4];
                ldsm4(bt, kAdr[p] + koff);
                mma_f16(s[p * 2],     a, bt);
                mma_f16(s[p * 2 + 1], a, bt + 2);
            }
        }

        if (kb >= 2 * qb) {
            int r0 = qb * FBQ + wm + grp;
            int cb = kb * FBK + qk * 2;
#pragma unroll
            for (int nt = 0; nt < 8; nt++) {
                int c0 = cb + nt * 8;
                if (c0     > r0)     s[nt][0] = -1e30f;
                if (c0 + 1 > r0)     s[nt][1] = -1e30f;
                if (c0     > r0 + 8) s[nt][2] = -1e30f;
                if (c0 + 1 > r0 + 8) s[nt][3] = -1e30f;
            }
        }

        float mx0 = -1e30f, mx1 = -1e30f;
#pragma unroll
        for (int nt = 0; nt < 8; nt++) {
            mx0 = fmaxf(mx0, fmaxf(s[nt][0], s[nt][1]));
            mx1 = fmaxf(mx1, fmaxf(s[nt][2], s[nt][3]));
        }
        mx0 = fmaxf(mx0, __shfl_xor_sync(0xffffffffu, mx0, 1));
        mx0 = fmaxf(mx0, __shfl_xor_sync(0xffffffffu, mx0, 2));
        mx1 = fmaxf(mx1, __shfl_xor_sync(0xffffffffu, mx1, 1));
        mx1 = fmaxf(mx1, __shfl_xor_sync(0xffffffffu, mx1, 2));

        float mn0 = fmaxf(m0, mx0), mn1 = fmaxf(m1, mx1);
        float corr0 = __expf(m0 - mn0), corr1 = __expf(m1 - mn1);
        m0 = mn0; m1 = mn1;

        float rs0 = 0.f, rs1 = 0.f;
#pragma unroll
        for (int nt = 0; nt < 8; nt++) {
            float p0 = __expf(s[nt][0] - mn0);
            float p1 = __expf(s[nt][1] - mn0);
            float p2 = __expf(s[nt][2] - mn1);
            float p3 = __expf(s[nt][3] - mn1);
            rs0 += p0 + p1; rs1 += p2 + p3;
            Pw[(wm + grp)     * PW + nt * 4 + qk] = h2u(__floats2half2_rn(p0, p1));
            Pw[(wm + grp + 8) * PW + nt * 4 + qk] = h2u(__floats2half2_rn(p2, p3));
        }
        rs0 += __shfl_xor_sync(0xffffffffu, rs0, 1);
        rs0 += __shfl_xor_sync(0xffffffffu, rs0, 2);
        rs1 += __shfl_xor_sync(0xffffffffu, rs1, 1);
        rs1 += __shfl_xor_sync(0xffffffffu, rs1, 2);
        l0 = l0 * corr0 + rs0;
        l1 = l1 * corr1 + rs1;

#pragma unroll
        for (int nt = 0; nt < 16; nt++) {
            oacc[nt][0] *= corr0; oacc[nt][1] *= corr0;
            oacc[nt][2] *= corr1; oacc[nt][3] *= corr1;
        }
        __syncwarp();

#pragma unroll
        for (int ks = 0; ks < 4; ks++) {
            unsigned koff = ks * 32;
            unsigned a[4];
            ldsm4(a, pAdr + koff);
#pragma unroll
            for (int p = 0; p < 8; p++) {
                unsigned bt[4];
                ldsm4(bt, vAdr[p] + koff);
                mma_f16(oacc[p * 2],     a, bt);
                mma_f16(oacc[p * 2 + 1], a, bt + 2);
            }
        }
    }

    float inv0 = 1.0f / l0, inv1 = 1.0f / l1;
    int r0 = qb * FBQ + wm + grp;
    __half* out0 = o + ((size_t)(b * S_ + r0) * NH_ + h) * HD_;
    __half* out1 = o + ((size_t)(b * S_ + r0 + 8) * NH_ + h) * HD_;
#pragma unroll
    for (int nt = 0; nt < 16; nt++) {
        int col = nt * 8 + qk * 2;
        *(__half2*)(out0 + col) = __floats2half2_rn(oacc[nt][0] * inv0, oacc[nt][1] * inv0);
        *(__half2*)(out1 + col) = __floats2half2_rn(oacc[nt][2] * inv1, oacc[nt][3] * inv1);
    }
}

// ---------------------------------------------------------------------------
extern "C" void kernel_launch(void* const* d_in, const int* in_sizes, int n_in,
                              void* d_out, int out_size)
{
    const float* hidden = (const float*)d_in[0];
    const float* ln1_w = (const float*)d_in[3];
    const float* Wq    = (const float*)d_in[4];
    const float* Wk    = (const float*)d_in[5];
    const float* Wv    = (const float*)d_in[6];
    const float* Wo    = (const float*)d_in[7];
    const float* qn_w  = (const float*)d_in[8];
    const float* kn_w  = (const float*)d_in[9];
    const float* ln2_w = (const float*)d_in[10];
    const float* Wg    = (const float*)d_in[11];
    const float* Wu    = (const float*)d_in[12];
    const float* Wd    = (const float*)d_in[13];
    float* out = (float*)d_out;

    float *p_q, *p_k, *p_v, *p_x, *p_g;
    __half *p_hh, *p_oh, *p_gh;
    __half *p_wqT, *p_wkT, *p_wvT, *p_woT, *p_wgT, *p_wuT, *p_wdT;
    cudaGetSymbolAddress((void**)&p_q, g_q);
    cudaGetSymbolAddress((void**)&p_k, g_k);
    cudaGetSymbolAddress((void**)&p_v, g_v);
    cudaGetSymbolAddress((void**)&p_x, g_x);
    cudaGetSymbolAddress((void**)&p_g, g_g);
    cudaGetSymbolAddress((void**)&p_hh, g_hh);
    cudaGetSymbolAddress((void**)&p_oh, g_oh);
    cudaGetSymbolAddress((void**)&p_gh, g_gh);
    cudaGetSymbolAddress((void**)&p_wqT, g_wqT);
    cudaGetSymbolAddress((void**)&p_wkT, g_wkT);
    cudaGetSymbolAddress((void**)&p_wvT, g_wvT);
    cudaGetSymbolAddress((void**)&p_woT, g_woT);
    cudaGetSymbolAddress((void**)&p_wgT, g_wgT);
    cudaGetSymbolAddress((void**)&p_wuT, g_wuT);
    cudaGetSymbolAddress((void**)&p_wdT, g_wdT);

    cudaFuncSetAttribute(flash_kernel,
                         cudaFuncAttributeMaxDynamicSharedMemorySize, FLASH_SMEM);
    cudaFuncSetAttribute(gemm_h_kernel,
                         cudaFuncAttributeMaxDynamicSharedMemorySize, HG_SMEM);

    rope_table_kernel<<<(S_ * 64 + 255) / 256, 256>>>();

    dim3 tb(32, 8);
    transpose_cvt_kernel<<<dim3(64, 64),  tb>>>(Wq, p_wqT, 2048, 2048);
    transpose_cvt_kernel<<<dim3(64, 16),  tb>>>(Wk, p_wkT, 2048, 512);
    transpose_cvt_kernel<<<dim3(64, 16),  tb>>>(Wv, p_wvT, 2048, 512);
    transpose_cvt_kernel<<<dim3(64, 64),  tb>>>(Wo, p_woT, 2048, 2048);
    transpose_cvt_kernel<<<dim3(64, 256), tb>>>(Wg, p_wgT, 2048, 8192);
    transpose_cvt_kernel<<<dim3(64, 256), tb>>>(Wu, p_wuT, 2048, 8192);
    transpose_cvt_kernel<<<dim3(256, 64), tb>>>(Wd, p_wdT, 8192, 2048);

    // Attention block
    rmsnorm_kernel<<<NTOK, 256>>>(hidden, ln1_w, p_hh);
    gemm_h_kernel<<<dim3((NH_ * HD_) / 128, NTOK / 128, 1), 256, HG_SMEM>>>(
        p_hh, p_wqT, nullptr, nullptr, p_q, nullptr, NTOK, NH_ * HD_, H_, 0);
    gemm_h_kernel<<<dim3((NKV_ * HD_) / 128, NTOK / 128, 2), 256, HG_SMEM>>>(
        p_hh, p_wkT, p_wvT, nullptr, p_k, p_v, NTOK, NKV_ * HD_, H_, 0);
    rope_norm_kernel<<<dim3(NTOK, NH_ / 4), 128>>>(p_q, qn_w, NH_);
    rope_norm_kernel<<<dim3(NTOK, NKV_ / 4), 128>>>(p_k, kn_w, NKV_);
    flash_kernel<<<dim3(S_ / FBQ, B_ * NH_), 256, FLASH_SMEM>>>(p_q, p_k, p_v, p_oh);
    gemm_h_kernel<<<dim3(H_ / 128, NTOK / 128, 1), 256, HG_SMEM>>>(
        p_oh, p_woT, nullptr, hidden, p_x, nullptr, NTOK, H_, H_, 0);

    // MLP block
    rmsnorm_kernel<<<NTOK, 256>>>(p_x, ln2_w, p_hh);
    gemm_h_kernel<<<dim3(I_ / 128, NTOK / 128, 1), 256, HG_SMEM>>>(
        p_hh, p_wgT, nullptr, nullptr, p_g, nullptr, NTOK, I_, H_, 0);
    gemm_h_kernel<<<dim3(I_ / 128, NTOK / 128, 1), 256, HG_SMEM>>>(
        p_hh, p_wuT, nullptr, p_g, (float*)p_gh, nullptr, NTOK, I_, H_, 1);
    gemm_h_kernel<<<dim3(H_ / 128, NTOK / 128, 1), 256, HG_SMEM>>>(
        p_gh, p_wdT, nullptr, p_x, out, nullptr, NTOK, H_, I_, 0);
}

// round 13
// speedup vs baseline: 1.1923x; 1.1923x over previous
#include <cuda_runtime.h>
#include <cuda_fp16.h>
#include <math.h>
#include <stdint.h>

#define B_   2
#define S_   2048
#define H_   2048
#define NH_  16
#define NKV_ 4
#define HD_  128
#define I_   8192
#define NTOK (B_*S_)
#define EPSF 1e-6f

// ---------------------------------------------------------------------------
__device__ float  g_q [NTOK * NH_ * HD_];
__device__ float  g_k [NTOK * NKV_ * HD_];
__device__ float  g_v [NTOK * NKV_ * HD_];
__device__ float  g_x [NTOK * H_];
__device__ float  g_g [NTOK * I_];
__device__ float  g_rope[S_ * HD_];
__device__ __half g_hh [NTOK * H_];
__device__ __half g_oh [NTOK * NH_ * HD_];
__device__ __half g_gh [NTOK * I_];
__device__ __half g_wqT[2048 * 2048];
__device__ __half g_wkT[512 * 2048];
__device__ __half g_wvT[512 * 2048];
__device__ __half g_woT[2048 * 2048];
__device__ __half g_wgT[8192 * 2048];
__device__ __half g_wuT[8192 * 2048];
__device__ __half g_wdT[2048 * 8192];

// ---------------------------------------------------------------------------
__device__ __forceinline__ void mma_f16(float* c, const unsigned* a, const unsigned* b) {
    asm volatile(
        "mma.sync.aligned.m16n8k16.row.col.f32.f16.f16.f32 "
        "{%0,%1,%2,%3},{%4,%5,%6,%7},{%8,%9},{%0,%1,%2,%3};\n"
        : "+f"(c[0]), "+f"(c[1]), "+f"(c[2]), "+f"(c[3])
        : "r"(a[0]), "r"(a[1]), "r"(a[2]), "r"(a[3]), "r"(b[0]), "r"(b[1]));
}

__device__ __forceinline__ void ldsm4(unsigned* r, unsigned addr) {
    asm volatile("ldmatrix.sync.aligned.m8n8.x4.shared.b16 {%0,%1,%2,%3}, [%4];"
        : "=r"(r[0]), "=r"(r[1]), "=r"(r[2]), "=r"(r[3]) : "r"(addr));
}

__device__ __forceinline__ unsigned h2u(__half2 h) {
    return *(unsigned*)&h;
}

__device__ __forceinline__ unsigned smem_u32(const void* p) {
    return (unsigned)__cvta_generic_to_shared(p);
}

#define CP_ASYNC16(dst, src) \
    asm volatile("cp.async.ca.shared.global [%0], [%1], 16;" :: "r"(dst), "l"(src))
#define CP_COMMIT() asm volatile("cp.async.commit_group;" ::: "memory")
#define CP_WAIT(n)  asm volatile("cp.async.wait_group %0;" :: "n"(n) : "memory")

// ---------------------------------------------------------------------------
__global__ void rope_table_kernel() {
    int idx = blockIdx.x * blockDim.x + threadIdx.x;
    if (idx >= S_ * 64) return;
    int pos = idx >> 6;
    int i   = idx & 63;
    float invf = 1.0f / powf(10000.0f, (float)i / 64.0f);
    float ang  = (float)pos * invf;
    g_rope[pos * HD_ + i]      = cosf(ang);
    g_rope[pos * HD_ + 64 + i] = sinf(ang);
}

// ---------------------------------------------------------------------------
__global__ __launch_bounds__(256) void transpose_cvt_kernel(
    const float* __restrict__ W, __half* __restrict__ Wt, int K, int N)
{
    __shared__ float t[32][33];
    int k0 = blockIdx.x * 32, n0 = blockIdx.y * 32;
    int tx = threadIdx.x, ty = threadIdx.y;
#pragma unroll
    for (int j = ty; j < 32; j += 8)
        t[j][tx] = W[(size_t)(k0 + j) * N + n0 + tx];
    __syncthreads();
    if (tx < 16) {
#pragma unroll
        for (int j = ty; j < 32; j += 8) {
            __half2 hv = __floats2half2_rn(t[2 * tx][j], t[2 * tx + 1][j]);
            *(__half2*)(Wt + (size_t)(n0 + j) * K + k0 + 2 * tx) = hv;
        }
    }
}

// ---------------------------------------------------------------------------
__global__ __launch_bounds__(256) void rmsnorm_kernel(
    const float* __restrict__ x, const float* __restrict__ w,
    __half* __restrict__ out)
{
    int row = blockIdx.x;
    const float* xr = x + (size_t)row * H_;
    float ss = 0.f;
#pragma unroll
    for (int it = 0; it < H_ / (256 * 4); it++) {
        int c = (it * 256 + threadIdx.x) * 4;
        float4 t = *(const float4*)(xr + c);
        ss += t.x * t.x + t.y * t.y + t.z * t.z + t.w * t.w;
    }
#pragma unroll
    for (int o = 16; o; o >>= 1) ss += __shfl_xor_sync(0xffffffffu, ss, o);
    __shared__ float red[8];
    if ((threadIdx.x & 31) == 0) red[threadIdx.x >> 5] = ss;
    __syncthreads();
    float tot = 0.f;
#pragma unroll
    for (int i = 0; i < 8; i++) tot += red[i];
    float inv = rsqrtf(tot * (1.0f / H_) + EPSF);
    __half* orow = out + (size_t)row * H_;
#pragma unroll
    for (int it = 0; it < H_ / (256 * 4); it++) {
        int c = (it * 256 + threadIdx.x) * 4;
        float4 t  = *(const float4*)(xr + c);
        float4 wv = *(const float4*)(w + c);
        __half2 h0 = __floats2half2_rn(wv.x * t.x * inv, wv.y * t.y * inv);
        __half2 h1 = __floats2half2_rn(wv.z * t.z * inv, wv.w * t.w * inv);
        *(__half2*)(orow + c)     = h0;
        *(__half2*)(orow + c + 2) = h1;
    }
}

// ---------------------------------------------------------------------------
// FP16 GEMM: cp.async 2-stage, ldmatrix, 2 CTAs/SM (R11 pipeline).
// mode 0: C fp32 (+optional addend). mode 1: C = half(silu(addend)*acc).
// ---------------------------------------------------------------------------
#define HSTR 72
#define HBUF (128 * HSTR)
#define HG_SMEM (4 * HBUF * 2)

__global__ __launch_bounds__(256, 2) void gemm_h_kernel(
    const __half* __restrict__ A, const __half* __restrict__ Bt,
    const __half* __restrict__ Bt2, const float* __restrict__ addend,
    float* __restrict__ C, float* __restrict__ C2,
    int M, int N, int K, int mode)
{
    extern __shared__ __half smh[];
    __half* As0 = smh;
    __half* Bs0 = smh + HBUF;
    __half* As1 = smh + 2 * HBUF;
    __half* Bs1 = smh + 3 * HBUF;

    if (blockIdx.z == 1) { Bt = Bt2; C = C2; }

    int tid = threadIdx.x;
    int bm = blockIdx.y * 128, bn = blockIdx.x * 128;
    int wid = tid >> 5, lane = tid & 31;
    int wm = (wid & 1) * 64;
    int wn = (wid >> 1) * 32;
    int grp = lane >> 2, qk = lane & 3;

    int lrow = tid >> 3;
    int lseg = (tid & 7) * 8;

    const __half* Ag = A  + (size_t)(bm + lrow) * K + lseg;
    const __half* Bg = Bt + (size_t)(bn + lrow) * K + lseg;

    unsigned sa[2], sb[2];
    sa[0] = smem_u32(As0 + lrow * HSTR + lseg);
    sb[0] = smem_u32(Bs0 + lrow * HSTR + lseg);
    sa[1] = smem_u32(As1 + lrow * HSTR + lseg);
    sb[1] = smem_u32(Bs1 + lrow * HSTR + lseg);
    const unsigned rowstep = 32 * HSTR * 2;

    // ldmatrix per-lane addresses
    int mi = lane >> 3, lr = lane & 7;
    int miL = mi & 1, miH = mi >> 1;
    unsigned aAdr[2][4], bAdr[2][2];
#pragma unroll
    for (int mt = 0; mt < 4; mt++) {
        int rowA = wm + mt * 16 + miL * 8 + lr;
        aAdr[0][mt] = smem_u32(As0) + rowA * 144 + miH * 16;
        aAdr[1][mt] = smem_u32(As1) + rowA * 144 + miH * 16;
    }
#pragma unroll
    for (int p = 0; p < 2; p++) {
        int rowB = wn + p * 16 + miH * 8 + lr;
        bAdr[0][p] = smem_u32(Bs0) + rowB * 144 + miL * 16;
        bAdr[1][p] = smem_u32(Bs1) + rowB * 144 + miL * 16;
    }

    float acc[4][4][4];
#pragma unroll
    for (int mt = 0; mt < 4; mt++)
#pragma unroll
        for (int nt = 0; nt < 4; nt++)
#pragma unroll
            for (int r = 0; r < 4; r++) acc[mt][nt][r] = 0.f;

    int nk = K / 64;

#pragma unroll
    for (int s = 0; s < 4; s++) {
        CP_ASYNC16(sa[0] + s * rowstep, Ag + (size_t)(32 * s) * K);
        CP_ASYNC16(sb[0] + s * rowstep, Bg + (size_t)(32 * s) * K);
    }
    CP_COMMIT();
    if (nk > 1) {
#pragma unroll
        for (int s = 0; s < 4; s++) {
            CP_ASYNC16(sa[1] + s * rowstep, Ag + (size_t)(32 * s) * K + 64);
            CP_ASYNC16(sb[1] + s * rowstep, Bg + (size_t)(32 * s) * K + 64);
        }
        CP_COMMIT();
        CP_WAIT(1);
    } else {
        CP_WAIT(0);
    }
    __syncthreads();

    for (int kt = 0; kt < nk; kt++) {
        int cur = kt & 1;

#pragma unroll
        for (int ks = 0; ks < 4; ks++) {
            unsigned koff = ks * 32;
            unsigned afr[4][4], bfr[4][2], bt0[4], bt1[4];
#pragma unroll
            for (int mt = 0; mt < 4; mt++)
                ldsm4(afr[mt], aAdr[cur][mt] + koff);
            ldsm4(bt0, bAdr[cur][0] + koff);
            ldsm4(bt1, bAdr[cur][1] + koff);
            bfr[0][0] = bt0[0]; bfr[0][1] = bt0[1];
            bfr[1][0] = bt0[2]; bfr[1][1] = bt0[3];
            bfr[2][0] = bt1[0]; bfr[2][1] = bt1[1];
            bfr[3][0] = bt1[2]; bfr[3][1] = bt1[3];
#pragma unroll
            for (int mt = 0; mt < 4; mt++)
#pragma unroll
                for (int nt = 0; nt < 4; nt++)
                    mma_f16(acc[mt][nt], afr[mt], bfr[nt]);
        }
        __syncthreads();

        if (kt + 2 < nk) {
            const __half* Ag2 = Ag + (size_t)(kt + 2) * 64;
            const __half* Bg2 = Bg + (size_t)(kt + 2) * 64;
#pragma unroll
            for (int s = 0; s < 4; s++) {
                CP_ASYNC16(sa[cur] + s * rowstep, Ag2 + (size_t)(32 * s) * K);
                CP_ASYNC16(sb[cur] + s * rowstep, Bg2 + (size_t)(32 * s) * K);
            }
            CP_COMMIT();
            CP_WAIT(1);
            __syncthreads();
        } else if (kt + 1 < nk) {
            CP_WAIT(0);
            __syncthreads();
        }
    }

    if (mode == 0) {
#pragma unroll
        for (int mt = 0; mt < 4; mt++) {
#pragma unroll
            for (int nt = 0; nt < 4; nt++) {
                int row0 = bm + wm + mt * 16 + grp;
                int col  = bn + wn + nt * 8 + qk * 2;
                float* c0 = C + (size_t)row0 * N + col;
                float* c1 = C + (size_t)(row0 + 8) * N + col;
                if (addend) {
                    const float* a0 = addend + (size_t)row0 * N + col;
                    const float* a1 = addend + (size_t)(row0 + 8) * N + col;
                    *(float2*)c0 = make_float2(acc[mt][nt][0] + a0[0], acc[mt][nt][1] + a0[1]);
                    *(float2*)c1 = make_float2(acc[mt][nt][2] + a1[0], acc[mt][nt][3] + a1[1]);
                } else {
                    *(float2*)c0 = make_float2(acc[mt][nt][0], acc[mt][nt][1]);
                    *(float2*)c1 = make_float2(acc[mt][nt][2], acc[mt][nt][3]);
                }
            }
        }
    } else {
        // swiglu fusion: out_h = silu(g) * u   (g = addend, u = acc)
        __half* Ch = (__half*)C;
#pragma unroll
        for (int mt = 0; mt < 4; mt++) {
#pragma unroll
            for (int nt = 0; nt < 4; nt++) {
                int row0 = bm + wm + mt * 16 + grp;
                int col  = bn + wn + nt * 8 + qk * 2;
                const float* a0 = addend + (size_t)row0 * N + col;
                const float* a1 = addend + (size_t)(row0 + 8) * N + col;
                float g0 = a0[0], g1 = a0[1], g2 = a1[0], g3 = a1[1];
                float r0 = g0 / (1.f + __expf(-g0)) * acc[mt][nt][0];
                float r1 = g1 / (1.f + __expf(-g1)) * acc[mt][nt][1];
                float r2 = g2 / (1.f + __expf(-g2)) * acc[mt][nt][2];
                float r3 = g3 / (1.f + __expf(-g3)) * acc[mt][nt][3];
                *(__half2*)(Ch + (size_t)row0 * N + col)       = __floats2half2_rn(r0, r1);
                *(__half2*)(Ch + (size_t)(row0 + 8) * N + col) = __floats2half2_rn(r2, r3);
            }
        }
    }
}

// ---------------------------------------------------------------------------
__global__ __launch_bounds__(128) void rope_norm_kernel(
    float* __restrict__ qkp, const float* __restrict__ w, int nheads)
{
    int tok  = blockIdx.x;
    int warp = threadIdx.x >> 5;
    int lane = threadIdx.x & 31;
    int head = blockIdx.y * 4 + warp;
    int pos  = tok % S_;

    float* base = qkp + ((size_t)tok * nheads + head) * HD_;
    float a0 = base[lane];      float a1 = base[lane + 32];
    float b0 = base[lane + 64]; float b1 = base[lane + 96];

    const float* rc = g_rope + (size_t)pos * HD_;
    float c0 = rc[lane],      s0 = rc[64 + lane];
    float c1 = rc[lane + 32], s1 = rc[96 + lane];

    float r0  = a0 * c0 - b0 * s0;
    float r64 = b0 * c0 + a0 * s0;
    float r32 = a1 * c1 - b1 * s1;
    float r96 = b1 * c1 + a1 * s1;

    float ss = r0 * r0 + r32 * r32 + r64 * r64 + r96 * r96;
#pragma unroll
    for (int o = 16; o; o >>= 1) ss += __shfl_xor_sync(0xffffffffu, ss, o);
    float inv = rsqrtf(ss * (1.0f / HD_) + EPSF);

    base[lane]      = w[lane]      * r0  * inv;
    base[lane + 32] = w[lane + 32] * r32 * inv;
    base[lane + 64] = w[lane + 64] * r64 * inv;
    base[lane + 96] = w[lane + 96] * r96 * inv;
}

// ---------------------------------------------------------------------------
// FP16 flash attention with ldmatrix fragment feeds. BQ=128, BK=64.
// ---------------------------------------------------------------------------
#define FBQ 128
#define FBK 64
#define QKW 68
#define VTW 36
#define PW  36
#define QS_WORDS (FBQ * QKW)
#define KS_WORDS (FBK * QKW)
#define VT_WORDS (HD_ * VTW)
#define PS_WORDS (FBQ * PW)
#define FLASH_SMEM ((QS_WORDS + KS_WORDS + VT_WORDS + PS_WORDS) * 4)

__global__ __launch_bounds__(256, 2) void flash_kernel(
    const float* __restrict__ q, const float* __restrict__ k,
    const float* __restrict__ v, __half* __restrict__ o)
{
    extern __shared__ unsigned smw[];
    unsigned* Qw = smw;
    unsigned* Kw = Qw + QS_WORDS;
    unsigned* Vw = Kw + KS_WORDS;
    unsigned* Pw = Vw + VT_WORDS;

    int qb = gridDim.x - 1 - blockIdx.x;
    int bh = blockIdx.y;
    int b  = bh / NH_, h = bh % NH_;
    int kvh = h / (NH_ / NKV_);

    int tid = threadIdx.x;
    int wid = tid >> 5, lane = tid & 31;
    int wm = wid * 16;
    int grp = lane >> 2, qk = lane & 3;

    const float scale = 0.08838834764831845f;

    int mi = lane >> 3, lr = lane & 7;
    int miL = mi & 1, miH = mi >> 1;
    unsigned qAdr, pAdr, kAdr[4], vAdr[8];
    {
        int rowQ = wm + miL * 8 + lr;
        qAdr = smem_u32(Qw) + rowQ * 272 + miH * 16;
        int rowP = wm + miL * 8 + lr;
        pAdr = smem_u32(Pw) + rowP * 144 + miH * 16;
#pragma unroll
        for (int p = 0; p < 4; p++) {
            int rowK = p * 16 + miH * 8 + lr;
            kAdr[p] = smem_u32(Kw) + rowK * 272 + miL * 16;
        }
#pragma unroll
        for (int p = 0; p < 8; p++) {
            int rowV = p * 16 + miH * 8 + lr;
            vAdr[p] = smem_u32(Vw) + rowV * 144 + miL * 16;
        }
    }

    const float* qbase = q + ((size_t)(b * S_ + qb * FBQ) * NH_ + h) * HD_;
    for (int i = tid; i < FBQ * (HD_ / 4); i += 256) {
        int r  = i >> 5;
        int c4 = (i & 31) * 4;
        float4 t = *(const float4*)(qbase + (size_t)r * NH_ * HD_ + c4);
        unsigned* dst = Qw + r * QKW + (c4 >> 1);
        dst[0] = h2u(__floats2half2_rn(t.x * scale, t.y * scale));
        dst[1] = h2u(__floats2half2_rn(t.z * scale, t.w * scale));
    }

    float m0 = -1e30f, m1 = -1e30f, l0 = 0.f, l1 = 0.f;
    float oacc[16][4];
#pragma unroll
    for (int nt = 0; nt < 16; nt++)
#pragma unroll
        for (int r = 0; r < 4; r++) oacc[nt][r] = 0.f;

    int nkb = 2 * qb + 2;
    for (int kb = 0; kb < nkb; kb++) {
        __syncthreads();
        const float* kbase = k + ((size_t)(b * S_ + kb * FBK) * NKV_ + kvh) * HD_;
        const float* vbase = v + ((size_t)(b * S_ + kb * FBK) * NKV_ + kvh) * HD_;
        for (int i = tid; i < FBK * (HD_ / 4); i += 256) {
            int r  = i >> 5;
            int c4 = (i & 31) * 4;
            float4 tk = *(const float4*)(kbase + (size_t)r * NKV_ * HD_ + c4);
            unsigned* kd = Kw + r * QKW + (c4 >> 1);
            kd[0] = h2u(__floats2half2_rn(tk.x, tk.y));
            kd[1] = h2u(__floats2half2_rn(tk.z, tk.w));
        }
        for (int i = tid; i < 32 * 32; i += 256) {
            int sp = i & 31;
            int c4 = (i >> 5) * 4;
            float4 va = *(const float4*)(vbase + (size_t)(2 * sp)     * NKV_ * HD_ + c4);
            float4 vb = *(const float4*)(vbase + (size_t)(2 * sp + 1) * NKV_ * HD_ + c4);
            Vw[(c4 + 0) * VTW + sp] = h2u(__floats2half2_rn(va.x, vb.x));
            Vw[(c4 + 1) * VTW + sp] = h2u(__floats2half2_rn(va.y, vb.y));
            Vw[(c4 + 2) * VTW + sp] = h2u(__floats2half2_rn(va.z, vb.z));
            Vw[(c4 + 3) * VTW + sp] = h2u(__floats2half2_rn(va.w, vb.w));
        }
        __syncthreads();

        float s[8][4];
#pragma unroll
        for (int nt = 0; nt < 8; nt++)
#pragma unroll
            for (int r = 0; r < 4; r++) s[nt][r] = 0.f;

#pragma unroll
        for (int ks = 0; ks < 8; ks++) {
            unsigned koff = ks * 32;
            unsigned a[4];
            ldsm4(a, qAdr + koff);
#pragma unroll
            for (int p = 0; p < 4; p++) {
                unsigned bt[4];
                ldsm4(bt, kAdr[p] + koff);
                mma_f16(s[p * 2],     a, bt);
                mma_f16(s[p * 2 + 1], a, bt + 2);
            }
        }

        if (kb >= 2 * qb) {
            int r0 = qb * FBQ + wm + grp;
            int cb = kb * FBK + qk * 2;
#pragma unroll
            for (int nt = 0; nt < 8; nt++) {
                int c0 = cb + nt * 8;
                if (c0     > r0)     s[nt][0] = -1e30f;
                if (c0 + 1 > r0)     s[nt][1] = -1e30f;
                if (c0     > r0 + 8) s[nt][2] = -1e30f;
                if (c0 + 1 > r0 + 8) s[nt][3] = -1e30f;
            }
        }

        float mx0 = -1e30f, mx1 = -1e30f;
#pragma unroll
        for (int nt = 0; nt < 8; nt++) {
            mx0 = fmaxf(mx0, fmaxf(s[nt][0], s[nt][1]));
            mx1 = fmaxf(mx1, fmaxf(s[nt][2], s[nt][3]));
        }
        mx0 = fmaxf(mx0, __shfl_xor_sync(0xffffffffu, mx0, 1));
        mx0 = fmaxf(mx0, __shfl_xor_sync(0xffffffffu, mx0, 2));
        mx1 = fmaxf(mx1, __shfl_xor_sync(0xffffffffu, mx1, 1));
        mx1 = fmaxf(mx1, __shfl_xor_sync(0xffffffffu, mx1, 2));

        float mn0 = fmaxf(m0, mx0), mn1 = fmaxf(m1, mx1);
        float corr0 = __expf(m0 - mn0), corr1 = __expf(m1 - mn1);
        m0 = mn0; m1 = mn1;

        float rs0 = 0.f, rs1 = 0.f;
#pragma unroll
        for (int nt = 0; nt < 8; nt++) {
            float p0 = __expf(s[nt][0] - mn0);
            float p1 = __expf(s[nt][1] - mn0);
            float p2 = __expf(s[nt][2] - mn1);
            float p3 = __expf(s[nt][3] - mn1);
            rs0 += p0 + p1; rs1 += p2 + p3;
            Pw[(wm + grp)     * PW + nt * 4 + qk] = h2u(__floats2half2_rn(p0, p1));
            Pw[(wm + grp + 8) * PW + nt * 4 + qk] = h2u(__floats2half2_rn(p2, p3));
        }
        rs0 += __shfl_xor_sync(0xffffffffu, rs0, 1);
        rs0 += __shfl_xor_sync(0xffffffffu, rs0, 2);
        rs1 += __shfl_xor_sync(0xffffffffu, rs1, 1);
        rs1 += __shfl_xor_sync(0xffffffffu, rs1, 2);
        l0 = l0 * corr0 + rs0;
        l1 = l1 * corr1 + rs1;

#pragma unroll
        for (int nt = 0; nt < 16; nt++) {
            oacc[nt][0] *= corr0; oacc[nt][1] *= corr0;
            oacc[nt][2] *= corr1; oacc[nt][3] *= corr1;
        }
        __syncwarp();

#pragma unroll
        for (int ks = 0; ks < 4; ks++) {
            unsigned koff = ks * 32;
            unsigned a[4];
            ldsm4(a, pAdr + koff);
#pragma unroll
            for (int p = 0; p < 8; p++) {
                unsigned bt[4];
                ldsm4(bt, vAdr[p] + koff);
                mma_f16(oacc[p * 2],     a, bt);
                mma_f16(oacc[p * 2 + 1], a, bt + 2);
            }
        }
    }

    float inv0 = 1.0f / l0, inv1 = 1.0f / l1;
    int r0 = qb * FBQ + wm + grp;
    __half* out0 = o + ((size_t)(b * S_ + r0) * NH_ + h) * HD_;
    __half* out1 = o + ((size_t)(b * S_ + r0 + 8) * NH_ + h) * HD_;
#pragma unroll
    for (int nt = 0; nt < 16; nt++) {
        int col = nt * 8 + qk * 2;
        *(__half2*)(out0 + col) = __floats2half2_rn(oacc[nt][0] * inv0, oacc[nt][1] * inv0);
        *(__half2*)(out1 + col) = __floats2half2_rn(oacc[nt][2] * inv1, oacc[nt][3] * inv1);
    }
}

// ---------------------------------------------------------------------------
extern "C" void kernel_launch(void* const* d_in, const int* in_sizes, int n_in,
                              void* d_out, int out_size)
{
    const float* hidden = (const float*)d_in[0];
    const float* ln1_w = (const float*)d_in[3];
    const float* Wq    = (const float*)d_in[4];
    const float* Wk    = (const float*)d_in[5];
    const float* Wv    = (const float*)d_in[6];
    const float* Wo    = (const float*)d_in[7];
    const float* qn_w  = (const float*)d_in[8];
    const float* kn_w  = (const float*)d_in[9];
    const float* ln2_w = (const float*)d_in[10];
    const float* Wg    = (const float*)d_in[11];
    const float* Wu    = (const float*)d_in[12];
    const float* Wd    = (const float*)d_in[13];
    float* out = (float*)d_out;

    float *p_q, *p_k, *p_v, *p_x, *p_g;
    __half *p_hh, *p_oh, *p_gh;
    __half *p_wqT, *p_wkT, *p_wvT, *p_woT, *p_wgT, *p_wuT, *p_wdT;
    cudaGetSymbolAddress((void**)&p_q, g_q);
    cudaGetSymbolAddress((void**)&p_k, g_k);
    cudaGetSymbolAddress((void**)&p_v, g_v);
    cudaGetSymbolAddress((void**)&p_x, g_x);
    cudaGetSymbolAddress((void**)&p_g, g_g);
    cudaGetSymbolAddress((void**)&p_hh, g_hh);
    cudaGetSymbolAddress((void**)&p_oh, g_oh);
    cudaGetSymbolAddress((void**)&p_gh, g_gh);
    cudaGetSymbolAddress((void**)&p_wqT, g_wqT);
    cudaGetSymbolAddress((void**)&p_wkT, g_wkT);
    cudaGetSymbolAddress((void**)&p_wvT, g_wvT);
    cudaGetSymbolAddress((void**)&p_woT, g_woT);
    cudaGetSymbolAddress((void**)&p_wgT, g_wgT);
    cudaGetSymbolAddress((void**)&p_wuT, g_wuT);
    cudaGetSymbolAddress((void**)&p_wdT, g_wdT);

    cudaFuncSetAttribute(flash_kernel,
                         cudaFuncAttributeMaxDynamicSharedMemorySize, FLASH_SMEM);
    cudaFuncSetAttribute(gemm_h_kernel,
                         cudaFuncAttributeMaxDynamicSharedMemorySize, HG_SMEM);

    rope_table_kernel<<<(S_ * 64 + 255) / 256, 256>>>();

    dim3 tb(32, 8);
    transpose_cvt_kernel<<<dim3(64, 64),  tb>>>(Wq, p_wqT, 2048, 2048);
    transpose_cvt_kernel<<<dim3(64, 16),  tb>>>(Wk, p_wkT, 2048, 512);
    transpose_cvt_kernel<<<dim3(64, 16),  tb>>>(Wv, p_wvT, 2048, 512);
    transpose_cvt_kernel<<<dim3(64, 64),  tb>>>(Wo, p_woT, 2048, 2048);
    transpose_cvt_kernel<<<dim3(64, 256), tb>>>(Wg, p_wgT, 2048, 8192);
    transpose_cvt_kernel<<<dim3(64, 256), tb>>>(Wu, p_wuT, 2048, 8192);
    transpose_cvt_kernel<<<dim3(256, 64), tb>>>(Wd, p_wdT, 8192, 2048);

    // Attention block
    rmsnorm_kernel<<<NTOK, 256>>>(hidden, ln1_w, p_hh);
    gemm_h_kernel<<<dim3((NH_ * HD_) / 128, NTOK / 128, 1), 256, HG_SMEM>>>(
        p_hh, p_wqT, nullptr, nullptr, p_q, nullptr, NTOK, NH_ * HD_, H_, 0);
    gemm_h_kernel<<<dim3((NKV_ * HD_) / 128, NTOK / 128, 2), 256, HG_SMEM>>>(
        p_hh, p_wkT, p_wvT, nullptr, p_k, p_v, NTOK, NKV_ * HD_, H_, 0);
    rope_norm_kernel<<<dim3(NTOK, NH_ / 4), 128>>>(p_q, qn_w, NH_);
    rope_norm_kernel<<<dim3(NTOK, NKV_ / 4), 128>>>(p_k, kn_w, NKV_);
    flash_kernel<<<dim3(S_ / FBQ, B_ * NH_), 256, FLASH_SMEM>>>(p_q, p_k, p_v, p_oh);
    gemm_h_kernel<<<dim3(H_ / 128, NTOK / 128, 1), 256, HG_SMEM>>>(
        p_oh, p_woT, nullptr, hidden, p_x, nullptr, NTOK, H_, H_, 0);

    // MLP block
    rmsnorm_kernel<<<NTOK, 256>>>(p_x, ln2_w, p_hh);
    gemm_h_kernel<<<dim3(I_ / 128, NTOK / 128, 1), 256, HG_SMEM>>>(
        p_hh, p_wgT, nullptr, nullptr, p_g, nullptr, NTOK, I_, H_, 0);
    gemm_h_kernel<<<dim3(I_ / 128, NTOK / 128, 1), 256, HG_SMEM>>>(
        p_hh, p_wuT, nullptr, p_g, (float*)p_gh, nullptr, NTOK, I_, H_, 1);
    gemm_h_kernel<<<dim3(H_ / 128, NTOK / 128, 1), 256, HG_SMEM>>>(
        p_gh, p_wdT, nullptr, p_x, out, nullptr, NTOK, H_, I_, 0);
}

// round 14
// speedup vs baseline: 1.1989x; 1.0055x over previous
#include <cuda_runtime.h>
#include <cuda_fp16.h>
#include <math.h>
#include <stdint.h>

#define B_   2
#define S_   2048
#define H_   2048
#define NH_  16
#define NKV_ 4
#define HD_  128
#define I_   8192
#define NTOK (B_*S_)
#define EPSF 1e-6f

// ---------------------------------------------------------------------------
__device__ float  g_q [NTOK * NH_ * HD_];
__device__ float  g_k [NTOK * NKV_ * HD_];
__device__ float  g_x [NTOK * H_];
__device__ float  g_g [NTOK * I_];
__device__ float  g_rope[S_ * HD_];
__device__ __half g_qh [NTOK * NH_ * HD_];
__device__ __half g_kh [NTOK * NKV_ * HD_];
__device__ __half g_vh [NTOK * NKV_ * HD_];
__device__ __half g_hh [NTOK * H_];
__device__ __half g_oh [NTOK * NH_ * HD_];
__device__ __half g_gh [NTOK * I_];
__device__ __half g_wqT[2048 * 2048];
__device__ __half g_wkT[512 * 2048];
__device__ __half g_wvT[512 * 2048];
__device__ __half g_woT[2048 * 2048];
__device__ __half g_wgT[8192 * 2048];
__device__ __half g_wuT[8192 * 2048];
__device__ __half g_wdT[2048 * 8192];

// ---------------------------------------------------------------------------
__device__ __forceinline__ void mma_f16(float* c, const unsigned* a, const unsigned* b) {
    asm volatile(
        "mma.sync.aligned.m16n8k16.row.col.f32.f16.f16.f32 "
        "{%0,%1,%2,%3},{%4,%5,%6,%7},{%8,%9},{%0,%1,%2,%3};\n"
        : "+f"(c[0]), "+f"(c[1]), "+f"(c[2]), "+f"(c[3])
        : "r"(a[0]), "r"(a[1]), "r"(a[2]), "r"(a[3]), "r"(b[0]), "r"(b[1]));
}

__device__ __forceinline__ void ldsm4(unsigned* r, unsigned addr) {
    asm volatile("ldmatrix.sync.aligned.m8n8.x4.shared.b16 {%0,%1,%2,%3}, [%4];"
        : "=r"(r[0]), "=r"(r[1]), "=r"(r[2]), "=r"(r[3]) : "r"(addr));
}

__device__ __forceinline__ unsigned h2u(__half2 h) {
    return *(unsigned*)&h;
}

__device__ __forceinline__ unsigned smem_u32(const void* p) {
    return (unsigned)__cvta_generic_to_shared(p);
}

#define CP_ASYNC16(dst, src) \
    asm volatile("cp.async.ca.shared.global [%0], [%1], 16;" :: "r"(dst), "l"(src))
#define CP_COMMIT() asm volatile("cp.async.commit_group;" ::: "memory")
#define CP_WAIT(n)  asm volatile("cp.async.wait_group %0;" :: "n"(n) : "memory")

// ---------------------------------------------------------------------------
__global__ void rope_table_kernel() {
    int idx = blockIdx.x * blockDim.x + threadIdx.x;
    if (idx >= S_ * 64) return;
    int pos = idx >> 6;
    int i   = idx & 63;
    float invf = 1.0f / powf(10000.0f, (float)i / 64.0f);
    float ang  = (float)pos * invf;
    g_rope[pos * HD_ + i]      = cosf(ang);
    g_rope[pos * HD_ + 64 + i] = sinf(ang);
}

// ---------------------------------------------------------------------------
__global__ __launch_bounds__(256) void transpose_cvt_kernel(
    const float* __restrict__ W, __half* __restrict__ Wt, int K, int N)
{
    __shared__ float t[32][33];
    int k0 = blockIdx.x * 32, n0 = blockIdx.y * 32;
    int tx = threadIdx.x, ty = threadIdx.y;
#pragma unroll
    for (int j = ty; j < 32; j += 8)
        t[j][tx] = W[(size_t)(k0 + j) * N + n0 + tx];
    __syncthreads();
    if (tx < 16) {
#pragma unroll
        for (int j = ty; j < 32; j += 8) {
            __half2 hv = __floats2half2_rn(t[2 * tx][j], t[2 * tx + 1][j]);
            *(__half2*)(Wt + (size_t)(n0 + j) * K + k0 + 2 * tx) = hv;
        }
    }
}

// ---------------------------------------------------------------------------
__global__ __launch_bounds__(256) void rmsnorm_kernel(
    const float* __restrict__ x, const float* __restrict__ w,
    __half* __restrict__ out)
{
    int row = blockIdx.x;
    const float* xr = x + (size_t)row * H_;
    float ss = 0.f;
#pragma unroll
    for (int it = 0; it < H_ / (256 * 4); it++) {
        int c = (it * 256 + threadIdx.x) * 4;
        float4 t = *(const float4*)(xr + c);
        ss += t.x * t.x + t.y * t.y + t.z * t.z + t.w * t.w;
    }
#pragma unroll
    for (int o = 16; o; o >>= 1) ss += __shfl_xor_sync(0xffffffffu, ss, o);
    __shared__ float red[8];
    if ((threadIdx.x & 31) == 0) red[threadIdx.x >> 5] = ss;
    __syncthreads();
    float tot = 0.f;
#pragma unroll
    for (int i = 0; i < 8; i++) tot += red[i];
    float inv = rsqrtf(tot * (1.0f / H_) + EPSF);
    __half* orow = out + (size_t)row * H_;
#pragma unroll
    for (int it = 0; it < H_ / (256 * 4); it++) {
        int c = (it * 256 + threadIdx.x) * 4;
        float4 t  = *(const float4*)(xr + c);
        float4 wv = *(const float4*)(w + c);
        __half2 h0 = __floats2half2_rn(wv.x * t.x * inv, wv.y * t.y * inv);
        __half2 h1 = __floats2half2_rn(wv.z * t.z * inv, wv.w * t.w * inv);
        *(__half2*)(orow + c)     = h0;
        *(__half2*)(orow + c + 2) = h1;
    }
}

// ---------------------------------------------------------------------------
// FP16 GEMM: cp.async 2-stage, ldmatrix, 2 CTAs/SM.
// mode (per-z nibble): 0 = fp32 C (+opt addend); 1 = C=half(silu(addend)*acc);
//                      2 = plain half C.
// ---------------------------------------------------------------------------
#define HSTR 72
#define HBUF (128 * HSTR)
#define HG_SMEM (4 * HBUF * 2)

__global__ __launch_bounds__(256, 2) void gemm_h_kernel(
    const __half* __restrict__ A, const __half* __restrict__ Bt,
    const __half* __restrict__ Bt2, const float* __restrict__ addend,
    float* __restrict__ C, float* __restrict__ C2,
    int M, int N, int K, int mode)
{
    extern __shared__ __half smh[];
    __half* As0 = smh;
    __half* Bs0 = smh + HBUF;
    __half* As1 = smh + 2 * HBUF;
    __half* Bs1 = smh + 3 * HBUF;

    if (blockIdx.z == 1) { Bt = Bt2; C = C2; mode >>= 4; }
    mode &= 15;

    int tid = threadIdx.x;
    int bm = blockIdx.y * 128, bn = blockIdx.x * 128;
    int wid = tid >> 5, lane = tid & 31;
    int wm = (wid & 1) * 64;
    int wn = (wid >> 1) * 32;
    int grp = lane >> 2, qk = lane & 3;

    int lrow = tid >> 3;
    int lseg = (tid & 7) * 8;

    const __half* Ag = A  + (size_t)(bm + lrow) * K + lseg;
    const __half* Bg = Bt + (size_t)(bn + lrow) * K + lseg;

    unsigned sa[2], sb[2];
    sa[0] = smem_u32(As0 + lrow * HSTR + lseg);
    sb[0] = smem_u32(Bs0 + lrow * HSTR + lseg);
    sa[1] = smem_u32(As1 + lrow * HSTR + lseg);
    sb[1] = smem_u32(Bs1 + lrow * HSTR + lseg);
    const unsigned rowstep = 32 * HSTR * 2;

    int mi = lane >> 3, lr = lane & 7;
    int miL = mi & 1, miH = mi >> 1;
    unsigned aAdr[2][4], bAdr[2][2];
#pragma unroll
    for (int mt = 0; mt < 4; mt++) {
        int rowA = wm + mt * 16 + miL * 8 + lr;
        aAdr[0][mt] = smem_u32(As0) + rowA * 144 + miH * 16;
        aAdr[1][mt] = smem_u32(As1) + rowA * 144 + miH * 16;
    }
#pragma unroll
    for (int p = 0; p < 2; p++) {
        int rowB = wn + p * 16 + miH * 8 + lr;
        bAdr[0][p] = smem_u32(Bs0) + rowB * 144 + miL * 16;
        bAdr[1][p] = smem_u32(Bs1) + rowB * 144 + miL * 16;
    }

    float acc[4][4][4];
#pragma unroll
    for (int mt = 0; mt < 4; mt++)
#pragma unroll
        for (int nt = 0; nt < 4; nt++)
#pragma unroll
            for (int r = 0; r < 4; r++) acc[mt][nt][r] = 0.f;

    int nk = K / 64;

#pragma unroll
    for (int s = 0; s < 4; s++) {
        CP_ASYNC16(sa[0] + s * rowstep, Ag + (size_t)(32 * s) * K);
        CP_ASYNC16(sb[0] + s * rowstep, Bg + (size_t)(32 * s) * K);
    }
    CP_COMMIT();
    if (nk > 1) {
#pragma unroll
        for (int s = 0; s < 4; s++) {
            CP_ASYNC16(sa[1] + s * rowstep, Ag + (size_t)(32 * s) * K + 64);
            CP_ASYNC16(sb[1] + s * rowstep, Bg + (size_t)(32 * s) * K + 64);
        }
        CP_COMMIT();
        CP_WAIT(1);
    } else {
        CP_WAIT(0);
    }
    __syncthreads();

    for (int kt = 0; kt < nk; kt++) {
        int cur = kt & 1;

#pragma unroll
        for (int ks = 0; ks < 4; ks++) {
            unsigned koff = ks * 32;
            unsigned afr[4][4], bfr[4][2], bt0[4], bt1[4];
#pragma unroll
            for (int mt = 0; mt < 4; mt++)
                ldsm4(afr[mt], aAdr[cur][mt] + koff);
            ldsm4(bt0, bAdr[cur][0] + koff);
            ldsm4(bt1, bAdr[cur][1] + koff);
            bfr[0][0] = bt0[0]; bfr[0][1] = bt0[1];
            bfr[1][0] = bt0[2]; bfr[1][1] = bt0[3];
            bfr[2][0] = bt1[0]; bfr[2][1] = bt1[1];
            bfr[3][0] = bt1[2]; bfr[3][1] = bt1[3];
#pragma unroll
            for (int mt = 0; mt < 4; mt++)
#pragma unroll
                for (int nt = 0; nt < 4; nt++)
                    mma_f16(acc[mt][nt], afr[mt], bfr[nt]);
        }
        __syncthreads();

        if (kt + 2 < nk) {
            const __half* Ag2 = Ag + (size_t)(kt + 2) * 64;
            const __half* Bg2 = Bg + (size_t)(kt + 2) * 64;
#pragma unroll
            for (int s = 0; s < 4; s++) {
                CP_ASYNC16(sa[cur] + s * rowstep, Ag2 + (size_t)(32 * s) * K);
                CP_ASYNC16(sb[cur] + s * rowstep, Bg2 + (size_t)(32 * s) * K);
            }
            CP_COMMIT();
            CP_WAIT(1);
            __syncthreads();
        } else if (kt + 1 < nk) {
            CP_WAIT(0);
            __syncthreads();
        }
    }

    if (mode == 0) {
#pragma unroll
        for (int mt = 0; mt < 4; mt++) {
#pragma unroll
            for (int nt = 0; nt < 4; nt++) {
                int row0 = bm + wm + mt * 16 + grp;
                int col  = bn + wn + nt * 8 + qk * 2;
                float* c0 = C + (size_t)row0 * N + col;
                float* c1 = C + (size_t)(row0 + 8) * N + col;
                if (addend) {
                    const float* a0 = addend + (size_t)row0 * N + col;
                    const float* a1 = addend + (size_t)(row0 + 8) * N + col;
                    *(float2*)c0 = make_float2(acc[mt][nt][0] + a0[0], acc[mt][nt][1] + a0[1]);
                    *(float2*)c1 = make_float2(acc[mt][nt][2] + a1[0], acc[mt][nt][3] + a1[1]);
                } else {
                    *(float2*)c0 = make_float2(acc[mt][nt][0], acc[mt][nt][1]);
                    *(float2*)c1 = make_float2(acc[mt][nt][2], acc[mt][nt][3]);
                }
            }
        }
    } else if (mode == 1) {
        __half* Ch = (__half*)C;
#pragma unroll
        for (int mt = 0; mt < 4; mt++) {
#pragma unroll
            for (int nt = 0; nt < 4; nt++) {
                int row0 = bm + wm + mt * 16 + grp;
                int col  = bn + wn + nt * 8 + qk * 2;
                const float* a0 = addend + (size_t)row0 * N + col;
                const float* a1 = addend + (size_t)(row0 + 8) * N + col;
                float g0 = a0[0], g1 = a0[1], g2 = a1[0], g3 = a1[1];
                float r0 = g0 / (1.f + __expf(-g0)) * acc[mt][nt][0];
                float r1 = g1 / (1.f + __expf(-g1)) * acc[mt][nt][1];
                float r2 = g2 / (1.f + __expf(-g2)) * acc[mt][nt][2];
                float r3 = g3 / (1.f + __expf(-g3)) * acc[mt][nt][3];
                *(__half2*)(Ch + (size_t)row0 * N + col)       = __floats2half2_rn(r0, r1);
                *(__half2*)(Ch + (size_t)(row0 + 8) * N + col) = __floats2half2_rn(r2, r3);
            }
        }
    } else {
        __half* Ch = (__half*)C;
#pragma unroll
        for (int mt = 0; mt < 4; mt++) {
#pragma unroll
            for (int nt = 0; nt < 4; nt++) {
                int row0 = bm + wm + mt * 16 + grp;
                int col  = bn + wn + nt * 8 + qk * 2;
                *(__half2*)(Ch + (size_t)row0 * N + col) =
                    __floats2half2_rn(acc[mt][nt][0], acc[mt][nt][1]);
                *(__half2*)(Ch + (size_t)(row0 + 8) * N + col) =
                    __floats2half2_rn(acc[mt][nt][2], acc[mt][nt][3]);
            }
        }
    }
}

// ---------------------------------------------------------------------------
// RoPE + QK RMSNorm: fp32 in, fp16 out (outscale folds 1/sqrt(hd) for Q).
// ---------------------------------------------------------------------------
__global__ __launch_bounds__(128) void rope_norm_kernel(
    const float* __restrict__ in, __half* __restrict__ outh,
    const float* __restrict__ w, int nheads, float outscale)
{
    int tok  = blockIdx.x;
    int warp = threadIdx.x >> 5;
    int lane = threadIdx.x & 31;
    int head = blockIdx.y * 4 + warp;
    int pos  = tok % S_;

    const float* base = in + ((size_t)tok * nheads + head) * HD_;
    float a0 = base[lane];      float a1 = base[lane + 32];
    float b0 = base[lane + 64]; float b1 = base[lane + 96];

    const float* rc = g_rope + (size_t)pos * HD_;
    float c0 = rc[lane],      s0 = rc[64 + lane];
    float c1 = rc[lane + 32], s1 = rc[96 + lane];

    float r0  = a0 * c0 - b0 * s0;
    float r64 = b0 * c0 + a0 * s0;
    float r32 = a1 * c1 - b1 * s1;
    float r96 = b1 * c1 + a1 * s1;

    float ss = r0 * r0 + r32 * r32 + r64 * r64 + r96 * r96;
#pragma unroll
    for (int o = 16; o; o >>= 1) ss += __shfl_xor_sync(0xffffffffu, ss, o);
    float inv = rsqrtf(ss * (1.0f / HD_) + EPSF) * outscale;

    __half* ob = outh + ((size_t)tok * nheads + head) * HD_;
    ob[lane]      = __float2half(w[lane]      * r0  * inv);
    ob[lane + 32] = __float2half(w[lane + 32] * r32 * inv);
    ob[lane + 64] = __float2half(w[lane + 64] * r64 * inv);
    ob[lane + 96] = __float2half(w[lane + 96] * r96 * inv);
}

// ---------------------------------------------------------------------------
// FP16 flash attention, fp16 inputs (pure copies into smem), ldmatrix feeds.
// ---------------------------------------------------------------------------
#define FBQ 128
#define FBK 64
#define QKW 68
#define VTW 36
#define PW  36
#define QS_WORDS (FBQ * QKW)
#define KS_WORDS (FBK * QKW)
#define VT_WORDS (HD_ * VTW)
#define PS_WORDS (FBQ * PW)
#define FLASH_SMEM ((QS_WORDS + KS_WORDS + VT_WORDS + PS_WORDS) * 4)

__global__ __launch_bounds__(256, 2) void flash_kernel(
    const __half* __restrict__ q, const __half* __restrict__ k,
    const __half* __restrict__ v, __half* __restrict__ o)
{
    extern __shared__ unsigned smw[];
    unsigned* Qw = smw;
    unsigned* Kw = Qw + QS_WORDS;
    unsigned* Vw = Kw + KS_WORDS;
    unsigned* Pw = Vw + VT_WORDS;

    int qb = gridDim.x - 1 - blockIdx.x;
    int bh = blockIdx.y;
    int b  = bh / NH_, h = bh % NH_;
    int kvh = h / (NH_ / NKV_);

    int tid = threadIdx.x;
    int wid = tid >> 5, lane = tid & 31;
    int wm = wid * 16;
    int grp = lane >> 2, qk = lane & 3;

    int mi = lane >> 3, lr = lane & 7;
    int miL = mi & 1, miH = mi >> 1;
    unsigned qAdr, pAdr, kAdr[4], vAdr[8];
    {
        int rowQ = wm + miL * 8 + lr;
        qAdr = smem_u32(Qw) + rowQ * 272 + miH * 16;
        int rowP = wm + miL * 8 + lr;
        pAdr = smem_u32(Pw) + rowP * 144 + miH * 16;
#pragma unroll
        for (int p = 0; p < 4; p++) {
            int rowK = p * 16 + miH * 8 + lr;
            kAdr[p] = smem_u32(Kw) + rowK * 272 + miL * 16;
        }
#pragma unroll
        for (int p = 0; p < 8; p++) {
            int rowV = p * 16 + miH * 8 + lr;
            vAdr[p] = smem_u32(Vw) + rowV * 144 + miL * 16;
        }
    }

    // Q tile: pure fp16 copy (Q pre-scaled by rope_norm)
    const __half* qbase = q + ((size_t)(b * S_ + qb * FBQ) * NH_ + h) * HD_;
    for (int i = tid; i < FBQ * 16; i += 256) {
        int r  = i >> 4;
        int w4 = (i & 15) * 4;
        uint4 t = *(const uint4*)(qbase + (size_t)r * NH_ * HD_ + w4 * 2);
        unsigned* dst = Qw + r * QKW + w4;
        dst[0] = t.x; dst[1] = t.y; dst[2] = t.z; dst[3] = t.w;
    }

    float m0 = -1e30f, m1 = -1e30f, l0 = 0.f, l1 = 0.f;
    float oacc[16][4];
#pragma unroll
    for (int nt = 0; nt < 16; nt++)
#pragma unroll
        for (int r = 0; r < 4; r++) oacc[nt][r] = 0.f;

    int nkb = 2 * qb + 2;
    for (int kb = 0; kb < nkb; kb++) {
        __syncthreads();
        const __half* kbase = k + ((size_t)(b * S_ + kb * FBK) * NKV_ + kvh) * HD_;
        const __half* vbase = v + ((size_t)(b * S_ + kb * FBK) * NKV_ + kvh) * HD_;
        for (int i = tid; i < FBK * 16; i += 256) {
            int r  = i >> 4;
            int w4 = (i & 15) * 4;
            uint4 t = *(const uint4*)(kbase + (size_t)r * NKV_ * HD_ + w4 * 2);
            unsigned* dst = Kw + r * QKW + w4;
            dst[0] = t.x; dst[1] = t.y; dst[2] = t.z; dst[3] = t.w;
        }
        // V: transposed pair-packed via integer repack
        for (int i = tid; i < 32 * 32; i += 256) {
            int sp = i & 31;
            int c4 = (i >> 5) * 4;
            uint2 va = *(const uint2*)(vbase + (size_t)(2 * sp)     * NKV_ * HD_ + c4);
            uint2 vb = *(const uint2*)(vbase + (size_t)(2 * sp + 1) * NKV_ * HD_ + c4);
            Vw[(c4 + 0) * VTW + sp] = (va.x & 0xFFFFu) | (vb.x << 16);
            Vw[(c4 + 1) * VTW + sp] = (va.x >> 16) | (vb.x & 0xFFFF0000u);
            Vw[(c4 + 2) * VTW + sp] = (va.y & 0xFFFFu) | (vb.y << 16);
            Vw[(c4 + 3) * VTW + sp] = (va.y >> 16) | (vb.y & 0xFFFF0000u);
        }
        __syncthreads();

        float s[8][4];
#pragma unroll
        for (int nt = 0; nt < 8; nt++)
#pragma unroll
            for (int r = 0; r < 4; r++) s[nt][r] = 0.f;

#pragma unroll
        for (int ks = 0; ks < 8; ks++) {
            unsigned koff = ks * 32;
            unsigned a[4];
            ldsm4(a, qAdr + koff);
#pragma unroll
            for (int p = 0; p < 4; p++) {
                unsigned bt[4];
                ldsm4(bt, kAdr[p] + koff);
                mma_f16(s[p * 2],     a, bt);
                mma_f16(s[p * 2 + 1], a, bt + 2);
            }
        }

        if (kb >= 2 * qb) {
            int r0 = qb * FBQ + wm + grp;
            int cb = kb * FBK + qk * 2;
#pragma unroll
            for (int nt = 0; nt < 8; nt++) {
                int c0 = cb + nt * 8;
                if (c0     > r0)     s[nt][0] = -1e30f;
                if (c0 + 1 > r0)     s[nt][1] = -1e30f;
                if (c0     > r0 + 8) s[nt][2] = -1e30f;
                if (c0 + 1 > r0 + 8) s[nt][3] = -1e30f;
            }
        }

        float mx0 = -1e30f, mx1 = -1e30f;
#pragma unroll
        for (int nt = 0; nt < 8; nt++) {
            mx0 = fmaxf(mx0, fmaxf(s[nt][0], s[nt][1]));
            mx1 = fmaxf(mx1, fmaxf(s[nt][2], s[nt][3]));
        }
        mx0 = fmaxf(mx0, __shfl_xor_sync(0xffffffffu, mx0, 1));
        mx0 = fmaxf(mx0, __shfl_xor_sync(0xffffffffu, mx0, 2));
        mx1 = fmaxf(mx1, __shfl_xor_sync(0xffffffffu, mx1, 1));
        mx1 = fmaxf(mx1, __shfl_xor_sync(0xffffffffu, mx1, 2));

        float mn0 = fmaxf(m0, mx0), mn1 = fmaxf(m1, mx1);
        float corr0 = __expf(m0 - mn0), corr1 = __expf(m1 - mn1);
        m0 = mn0; m1 = mn1;

        float rs0 = 0.f, rs1 = 0.f;
#pragma unroll
        for (int nt = 0; nt < 8; nt++) {
            float p0 = __expf(s[nt][0] - mn0);
            float p1 = __expf(s[nt][1] - mn0);
            float p2 = __expf(s[nt][2] - mn1);
            float p3 = __expf(s[nt][3] - mn1);
            rs0 += p0 + p1; rs1 += p2 + p3;
            Pw[(wm + grp)     * PW + nt * 4 + qk] = h2u(__floats2half2_rn(p0, p1));
            Pw[(wm + grp + 8) * PW + nt * 4 + qk] = h2u(__floats2half2_rn(p2, p3));
        }
        rs0 += __shfl_xor_sync(0xffffffffu, rs0, 1);
        rs0 += __shfl_xor_sync(0xffffffffu, rs0, 2);
        rs1 += __shfl_xor_sync(0xffffffffu, rs1, 1);
        rs1 += __shfl_xor_sync(0xffffffffu, rs1, 2);
        l0 = l0 * corr0 + rs0;
        l1 = l1 * corr1 + rs1;

#pragma unroll
        for (int nt = 0; nt < 16; nt++) {
            oacc[nt][0] *= corr0; oacc[nt][1] *= corr0;
            oacc[nt][2] *= corr1; oacc[nt][3] *= corr1;
        }
        __syncwarp();

#pragma unroll
        for (int ks = 0; ks < 4; ks++) {
            unsigned koff = ks * 32;
            unsigned a[4];
            ldsm4(a, pAdr + koff);
#pragma unroll
            for (int p = 0; p < 8; p++) {
                unsigned bt[4];
                ldsm4(bt, vAdr[p] + koff);
                mma_f16(oacc[p * 2],     a, bt);
                mma_f16(oacc[p * 2 + 1], a, bt + 2);
            }
        }
    }

    float inv0 = 1.0f / l0, inv1 = 1.0f / l1;
    int r0 = qb * FBQ + wm + grp;
    __half* out0 = o + ((size_t)(b * S_ + r0) * NH_ + h) * HD_;
    __half* out1 = o + ((size_t)(b * S_ + r0 + 8) * NH_ + h) * HD_;
#pragma unroll
    for (int nt = 0; nt < 16; nt++) {
        int col = nt * 8 + qk * 2;
        *(__half2*)(out0 + col) = __floats2half2_rn(oacc[nt][0] * inv0, oacc[nt][1] * inv0);
        *(__half2*)(out1 + col) = __floats2half2_rn(oacc[nt][2] * inv1, oacc[nt][3] * inv1);
    }
}

// ---------------------------------------------------------------------------
extern "C" void kernel_launch(void* const* d_in, const int* in_sizes, int n_in,
                              void* d_out, int out_size)
{
    const float* hidden = (const float*)d_in[0];
    const float* ln1_w = (const float*)d_in[3];
    const float* Wq    = (const float*)d_in[4];
    const float* Wk    = (const float*)d_in[5];
    const float* Wv    = (const float*)d_in[6];
    const float* Wo    = (const float*)d_in[7];
    const float* qn_w  = (const float*)d_in[8];
    const float* kn_w  = (const float*)d_in[9];
    const float* ln2_w = (const float*)d_in[10];
    const float* Wg    = (const float*)d_in[11];
    const float* Wu    = (const float*)d_in[12];
    const float* Wd    = (const float*)d_in[13];
    float* out = (float*)d_out;

    float *p_q, *p_k, *p_x, *p_g;
    __half *p_qh, *p_kh, *p_vh, *p_hh, *p_oh, *p_gh;
    __half *p_wqT, *p_wkT, *p_wvT, *p_woT, *p_wgT, *p_wuT, *p_wdT;
    cudaGetSymbolAddress((void**)&p_q, g_q);
    cudaGetSymbolAddress((void**)&p_k, g_k);
    cudaGetSymbolAddress((void**)&p_x, g_x);
    cudaGetSymbolAddress((void**)&p_g, g_g);
    cudaGetSymbolAddress((void**)&p_qh, g_qh);
    cudaGetSymbolAddress((void**)&p_kh, g_kh);
    cudaGetSymbolAddress((void**)&p_vh, g_vh);
    cudaGetSymbolAddress((void**)&p_hh, g_hh);
    cudaGetSymbolAddress((void**)&p_oh, g_oh);
    cudaGetSymbolAddress((void**)&p_gh, g_gh);
    cudaGetSymbolAddress((void**)&p_wqT, g_wqT);
    cudaGetSymbolAddress((void**)&p_wkT, g_wkT);
    cudaGetSymbolAddress((void**)&p_wvT, g_wvT);
    cudaGetSymbolAddress((void**)&p_woT, g_woT);
    cudaGetSymbolAddress((void**)&p_wgT, g_wgT);
    cudaGetSymbolAddress((void**)&p_wuT, g_wuT);
    cudaGetSymbolAddress((void**)&p_wdT, g_wdT);

    cudaFuncSetAttribute(flash_kernel,
                         cudaFuncAttributeMaxDynamicSharedMemorySize, FLASH_SMEM);
    cudaFuncSetAttribute(gemm_h_kernel,
                         cudaFuncAttributeMaxDynamicSharedMemorySize, HG_SMEM);

    rope_table_kernel<<<(S_ * 64 + 255) / 256, 256>>>();

    dim3 tb(32, 8);
    transpose_cvt_kernel<<<dim3(64, 64),  tb>>>(Wq, p_wqT, 2048, 2048);
    transpose_cvt_kernel<<<dim3(64, 16),  tb>>>(Wk, p_wkT, 2048, 512);
    transpose_cvt_kernel<<<dim3(64, 16),  tb>>>(Wv, p_wvT, 2048, 512);
    transpose_cvt_kernel<<<dim3(64, 64),  tb>>>(Wo, p_woT, 2048, 2048);
    transpose_cvt_kernel<<<dim3(64, 256), tb>>>(Wg, p_wgT, 2048, 8192);
    transpose_cvt_kernel<<<dim3(64, 256), tb>>>(Wu, p_wuT, 2048, 8192);
    transpose_cvt_kernel<<<dim3(256, 64), tb>>>(Wd, p_wdT, 8192, 2048);

    // Attention block
    rmsnorm_kernel<<<NTOK, 256>>>(hidden, ln1_w, p_hh);
    gemm_h_kernel<<<dim3((NH_ * HD_) / 128, NTOK / 128, 1), 256, HG_SMEM>>>(
        p_hh, p_wqT, nullptr, nullptr, p_q, nullptr, NTOK, NH_ * HD_, H_, 0);
    // K (fp32 out, z=0) + V (fp16 out, z=1) fused; mode nibble-packed
    gemm_h_kernel<<<dim3((NKV_ * HD_) / 128, NTOK / 128, 2), 256, HG_SMEM>>>(
        p_hh, p_wkT, p_wvT, nullptr, p_k, (float*)p_vh, NTOK, NKV_ * HD_, H_, 0 | (2 << 4));
    rope_norm_kernel<<<dim3(NTOK, NH_ / 4), 128>>>(p_q, p_qh, qn_w, NH_, 0.08838834764831845f);
    rope_norm_kernel<<<dim3(NTOK, NKV_ / 4), 128>>>(p_k, p_kh, kn_w, NKV_, 1.0f);
    flash_kernel<<<dim3(S_ / FBQ, B_ * NH_), 256, FLASH_SMEM>>>(p_qh, p_kh, p_vh, p_oh);
    gemm_h_kernel<<<dim3(H_ / 128, NTOK / 128, 1), 256, HG_SMEM>>>(
        p_oh, p_woT, nullptr, hidden, p_x, nullptr, NTOK, H_, H_, 0);

    // MLP block
    rmsnorm_kernel<<<NTOK, 256>>>(p_x, ln2_w, p_hh);
    gemm_h_kernel<<<dim3(I_ / 128, NTOK / 128, 1), 256, HG_SMEM>>>(
        p_hh, p_wgT, nullptr, nullptr, p_g, nullptr, NTOK, I_, H_, 0);
    gemm_h_kernel<<<dim3(I_ / 128, NTOK / 128, 1), 256, HG_SMEM>>>(
        p_hh, p_wuT, nullptr, p_g, (float*)p_gh, nullptr, NTOK, I_, H_, 1);
    gemm_h_kernel<<<dim3(H_ / 128, NTOK / 128, 1), 256, HG_SMEM>>>(
        p_gh, p_wdT, nullptr, p_x, out, nullptr, NTOK, H_, I_, 0);
}

// round 15
// speedup vs baseline: 1.2101x; 1.0093x over previous
#include <cuda_runtime.h>
#include <cuda_fp16.h>
#include <math.h>
#include <stdint.h>

#define B_   2
#define S_   2048
#define H_   2048
#define NH_  16
#define NKV_ 4
#define HD_  128
#define I_   8192
#define NTOK (B_*S_)
#define EPSF 1e-6f

// ---------------------------------------------------------------------------
__device__ float  g_q [NTOK * NH_ * HD_];
__device__ float  g_k [NTOK * NKV_ * HD_];
__device__ float  g_x [NTOK * H_];
__device__ float  g_g [NTOK * I_];
__device__ float  g_rope[S_ * HD_];
__device__ __half g_qh [NTOK * NH_ * HD_];
__device__ __half g_kh [NTOK * NKV_ * HD_];
__device__ __half g_vh [NTOK * NKV_ * HD_];
__device__ __half g_hh [NTOK * H_];
__device__ __half g_oh [NTOK * NH_ * HD_];
__device__ __half g_gh [NTOK * I_];
__device__ __half g_wqkvT[3072 * 2048];
__device__ __half g_woT[2048 * 2048];
__device__ __half g_wgT[8192 * 2048];
__device__ __half g_wuT[8192 * 2048];
__device__ __half g_wdT[2048 * 8192];

// ---------------------------------------------------------------------------
__device__ __forceinline__ void mma_f16(float* c, const unsigned* a, const unsigned* b) {
    asm volatile(
        "mma.sync.aligned.m16n8k16.row.col.f32.f16.f16.f32 "
        "{%0,%1,%2,%3},{%4,%5,%6,%7},{%8,%9},{%0,%1,%2,%3};\n"
        : "+f"(c[0]), "+f"(c[1]), "+f"(c[2]), "+f"(c[3])
        : "r"(a[0]), "r"(a[1]), "r"(a[2]), "r"(a[3]), "r"(b[0]), "r"(b[1]));
}

__device__ __forceinline__ void ldsm4(unsigned* r, unsigned addr) {
    asm volatile("ldmatrix.sync.aligned.m8n8.x4.shared.b16 {%0,%1,%2,%3}, [%4];"
        : "=r"(r[0]), "=r"(r[1]), "=r"(r[2]), "=r"(r[3]) : "r"(addr));
}

__device__ __forceinline__ unsigned h2u(__half2 h) {
    return *(unsigned*)&h;
}

__device__ __forceinline__ unsigned smem_u32(const void* p) {
    return (unsigned)__cvta_generic_to_shared(p);
}

#define CP_ASYNC16(dst, src) \
    asm volatile("cp.async.ca.shared.global [%0], [%1], 16;" :: "r"(dst), "l"(src))
#define CP_COMMIT() asm volatile("cp.async.commit_group;" ::: "memory")
#define CP_WAIT(n)  asm volatile("cp.async.wait_group %0;" :: "n"(n) : "memory")

// ---------------------------------------------------------------------------
__global__ void rope_table_kernel() {
    int idx = blockIdx.x * blockDim.x + threadIdx.x;
    if (idx >= S_ * 64) return;
    int pos = idx >> 6;
    int i   = idx & 63;
    float invf = 1.0f / powf(10000.0f, (float)i / 64.0f);
    float ang  = (float)pos * invf;
    g_rope[pos * HD_ + i]      = cosf(ang);
    g_rope[pos * HD_ + 64 + i] = sinf(ang);
}

// ---------------------------------------------------------------------------
// Transpose + fp16 cvt; optional second tensor selected by blockIdx.z.
// ---------------------------------------------------------------------------
__global__ __launch_bounds__(256) void transpose_cvt_kernel(
    const float* __restrict__ W, const float* __restrict__ W2,
    __half* __restrict__ Wt, __half* __restrict__ Wt2, int K, int N)
{
    __shared__ float t[32][33];
    if (blockIdx.z == 1) { W = W2; Wt = Wt2; }
    int k0 = blockIdx.x * 32, n0 = blockIdx.y * 32;
    int tx = threadIdx.x, ty = threadIdx.y;
#pragma unroll
    for (int j = ty; j < 32; j += 8)
        t[j][tx] = W[(size_t)(k0 + j) * N + n0 + tx];
    __syncthreads();
    if (tx < 16) {
#pragma unroll
        for (int j = ty; j < 32; j += 8) {
            __half2 hv = __floats2half2_rn(t[2 * tx][j], t[2 * tx + 1][j]);
            *(__half2*)(Wt + (size_t)(n0 + j) * K + k0 + 2 * tx) = hv;
        }
    }
}

// ---------------------------------------------------------------------------
__global__ __launch_bounds__(256) void rmsnorm_kernel(
    const float* __restrict__ x, const float* __restrict__ w,
    __half* __restrict__ out)
{
    int row = blockIdx.x;
    const float* xr = x + (size_t)row * H_;
    float ss = 0.f;
#pragma unroll
    for (int it = 0; it < H_ / (256 * 4); it++) {
        int c = (it * 256 + threadIdx.x) * 4;
        float4 t = *(const float4*)(xr + c);
        ss += t.x * t.x + t.y * t.y + t.z * t.z + t.w * t.w;
    }
#pragma unroll
    for (int o = 16; o; o >>= 1) ss += __shfl_xor_sync(0xffffffffu, ss, o);
    __shared__ float red[8];
    if ((threadIdx.x & 31) == 0) red[threadIdx.x >> 5] = ss;
    __syncthreads();
    float tot = 0.f;
#pragma unroll
    for (int i = 0; i < 8; i++) tot += red[i];
    float inv = rsqrtf(tot * (1.0f / H_) + EPSF);
    __half* orow = out + (size_t)row * H_;
#pragma unroll
    for (int it = 0; it < H_ / (256 * 4); it++) {
        int c = (it * 256 + threadIdx.x) * 4;
        float4 t  = *(const float4*)(xr + c);
        float4 wv = *(const float4*)(w + c);
        __half2 h0 = __floats2half2_rn(wv.x * t.x * inv, wv.y * t.y * inv);
        __half2 h1 = __floats2half2_rn(wv.z * t.z * inv, wv.w * t.w * inv);
        *(__half2*)(orow + c)     = h0;
        *(__half2*)(orow + c + 2) = h1;
    }
}

// ---------------------------------------------------------------------------
// FP16 GEMM: cp.async 2-stage, ldmatrix, 2 CTAs/SM.
// mode nibble (z-selected): 0 = fp32 C (+opt addend); 1 = silu-fuse -> half;
// 2 = plain half C; 3 = QKV routing epilogue (C=q f32, C2=k f32, C3=v f16).
// ---------------------------------------------------------------------------
#define HSTR 72
#define HBUF (128 * HSTR)
#define HG_SMEM (4 * HBUF * 2)

__global__ __launch_bounds__(256, 2) void gemm_h_kernel(
    const __half* __restrict__ A, const __half* __restrict__ Bt,
    const __half* __restrict__ Bt2, const float* __restrict__ addend,
    float* __restrict__ C, float* __restrict__ C2, __half* __restrict__ C3,
    int M, int N, int K, int mode)
{
    extern __shared__ __half smh[];
    __half* As0 = smh;
    __half* Bs0 = smh + HBUF;
    __half* As1 = smh + 2 * HBUF;
    __half* Bs1 = smh + 3 * HBUF;

    if (blockIdx.z == 1) { Bt = Bt2; C = C2; mode >>= 4; }
    mode &= 15;

    int tid = threadIdx.x;
    int bm = blockIdx.y * 128, bn = blockIdx.x * 128;
    int wid = tid >> 5, lane = tid & 31;
    int wm = (wid & 1) * 64;
    int wn = (wid >> 1) * 32;
    int grp = lane >> 2, qk = lane & 3;

    int lrow = tid >> 3;
    int lseg = (tid & 7) * 8;

    const __half* Ag = A  + (size_t)(bm + lrow) * K + lseg;
    const __half* Bg = Bt + (size_t)(bn + lrow) * K + lseg;

    unsigned sa[2], sb[2];
    sa[0] = smem_u32(As0 + lrow * HSTR + lseg);
    sb[0] = smem_u32(Bs0 + lrow * HSTR + lseg);
    sa[1] = smem_u32(As1 + lrow * HSTR + lseg);
    sb[1] = smem_u32(Bs1 + lrow * HSTR + lseg);
    const unsigned rowstep = 32 * HSTR * 2;

    int mi = lane >> 3, lr = lane & 7;
    int miL = mi & 1, miH = mi >> 1;
    unsigned aAdr[2][4], bAdr[2][2];
#pragma unroll
    for (int mt = 0; mt < 4; mt++) {
        int rowA = wm + mt * 16 + miL * 8 + lr;
        aAdr[0][mt] = smem_u32(As0) + rowA * 144 + miH * 16;
        aAdr[1][mt] = smem_u32(As1) + rowA * 144 + miH * 16;
    }
#pragma unroll
    for (int p = 0; p < 2; p++) {
        int rowB = wn + p * 16 + miH * 8 + lr;
        bAdr[0][p] = smem_u32(Bs0) + rowB * 144 + miL * 16;
        bAdr[1][p] = smem_u32(Bs1) + rowB * 144 + miL * 16;
    }

    float acc[4][4][4];
#pragma unroll
    for (int mt = 0; mt < 4; mt++)
#pragma unroll
        for (int nt = 0; nt < 4; nt++)
#pragma unroll
            for (int r = 0; r < 4; r++) acc[mt][nt][r] = 0.f;

    int nk = K / 64;

#pragma unroll
    for (int s = 0; s < 4; s++) {
        CP_ASYNC16(sa[0] + s * rowstep, Ag + (size_t)(32 * s) * K);
        CP_ASYNC16(sb[0] + s * rowstep, Bg + (size_t)(32 * s) * K);
    }
    CP_COMMIT();
    if (nk > 1) {
#pragma unroll
        for (int s = 0; s < 4; s++) {
            CP_ASYNC16(sa[1] + s * rowstep, Ag + (size_t)(32 * s) * K + 64);
            CP_ASYNC16(sb[1] + s * rowstep, Bg + (size_t)(32 * s) * K + 64);
        }
        CP_COMMIT();
        CP_WAIT(1);
    } else {
        CP_WAIT(0);
    }
    __syncthreads();

    for (int kt = 0; kt < nk; kt++) {
        int cur = kt & 1;

#pragma unroll
        for (int ks = 0; ks < 4; ks++) {
            unsigned koff = ks * 32;
            unsigned afr[4][4], bfr[4][2], bt0[4], bt1[4];
#pragma unroll
            for (int mt = 0; mt < 4; mt++)
                ldsm4(afr[mt], aAdr[cur][mt] + koff);
            ldsm4(bt0, bAdr[cur][0] + koff);
            ldsm4(bt1, bAdr[cur][1] + koff);
            bfr[0][0] = bt0[0]; bfr[0][1] = bt0[1];
            bfr[1][0] = bt0[2]; bfr[1][1] = bt0[3];
            bfr[2][0] = bt1[0]; bfr[2][1] = bt1[1];
            bfr[3][0] = bt1[2]; bfr[3][1] = bt1[3];
#pragma unroll
            for (int mt = 0; mt < 4; mt++)
#pragma unroll
                for (int nt = 0; nt < 4; nt++)
                    mma_f16(acc[mt][nt], afr[mt], bfr[nt]);
        }
        __syncthreads();

        if (kt + 2 < nk) {
            const __half* Ag2 = Ag + (size_t)(kt + 2) * 64;
            const __half* Bg2 = Bg + (size_t)(kt + 2) * 64;
#pragma unroll
            for (int s = 0; s < 4; s++) {
                CP_ASYNC16(sa[cur] + s * rowstep, Ag2 + (size_t)(32 * s) * K);
                CP_ASYNC16(sb[cur] + s * rowstep, Bg2 + (size_t)(32 * s) * K);
            }
            CP_COMMIT();
            CP_WAIT(1);
            __syncthreads();
        } else if (kt + 1 < nk) {
            CP_WAIT(0);
            __syncthreads();
        }
    }

    if (mode == 0) {
#pragma unroll
        for (int mt = 0; mt < 4; mt++) {
#pragma unroll
            for (int nt = 0; nt < 4; nt++) {
                int row0 = bm + wm + mt * 16 + grp;
                int col  = bn + wn + nt * 8 + qk * 2;
                float* c0 = C + (size_t)row0 * N + col;
                float* c1 = C + (size_t)(row0 + 8) * N + col;
                if (addend) {
                    const float* a0 = addend + (size_t)row0 * N + col;
                    const float* a1 = addend + (size_t)(row0 + 8) * N + col;
                    *(float2*)c0 = make_float2(acc[mt][nt][0] + a0[0], acc[mt][nt][1] + a0[1]);
                    *(float2*)c1 = make_float2(acc[mt][nt][2] + a1[0], acc[mt][nt][3] + a1[1]);
                } else {
                    *(float2*)c0 = make_float2(acc[mt][nt][0], acc[mt][nt][1]);
                    *(float2*)c1 = make_float2(acc[mt][nt][2], acc[mt][nt][3]);
                }
            }
        }
    } else if (mode == 1) {
        __half* Ch = (__half*)C;
#pragma unroll
        for (int mt = 0; mt < 4; mt++) {
#pragma unroll
            for (int nt = 0; nt < 4; nt++) {
                int row0 = bm + wm + mt * 16 + grp;
                int col  = bn + wn + nt * 8 + qk * 2;
                const float* a0 = addend + (size_t)row0 * N + col;
                const float* a1 = addend + (size_t)(row0 + 8) * N + col;
                float g0 = a0[0], g1 = a0[1], g2 = a1[0], g3 = a1[1];
                float r0 = g0 / (1.f + __expf(-g0)) * acc[mt][nt][0];
                float r1 = g1 / (1.f + __expf(-g1)) * acc[mt][nt][1];
                float r2 = g2 / (1.f + __expf(-g2)) * acc[mt][nt][2];
                float r3 = g3 / (1.f + __expf(-g3)) * acc[mt][nt][3];
                *(__half2*)(Ch + (size_t)row0 * N + col)       = __floats2half2_rn(r0, r1);
                *(__half2*)(Ch + (size_t)(row0 + 8) * N + col) = __floats2half2_rn(r2, r3);
            }
        }
    } else if (mode == 2) {
        __half* Ch = (__half*)C;
#pragma unroll
        for (int mt = 0; mt < 4; mt++) {
#pragma unroll
            for (int nt = 0; nt < 4; nt++) {
                int row0 = bm + wm + mt * 16 + grp;
                int col  = bn + wn + nt * 8 + qk * 2;
                *(__half2*)(Ch + (size_t)row0 * N + col) =
                    __floats2half2_rn(acc[mt][nt][0], acc[mt][nt][1]);
                *(__half2*)(Ch + (size_t)(row0 + 8) * N + col) =
                    __floats2half2_rn(acc[mt][nt][2], acc[mt][nt][3]);
            }
        }
    } else {
        // mode 3: QKV routing. bn uniform per CTA; boundaries at 2048, 2560.
        if (bn < 2048) {
#pragma unroll
            for (int mt = 0; mt < 4; mt++)
#pragma unroll
                for (int nt = 0; nt < 4; nt++) {
                    int row0 = bm + wm + mt * 16 + grp;
                    int col  = bn + wn + nt * 8 + qk * 2;
                    *(float2*)(C + (size_t)row0 * 2048 + col) =
                        make_float2(acc[mt][nt][0], acc[mt][nt][1]);
                    *(float2*)(C + (size_t)(row0 + 8) * 2048 + col) =
                        make_float2(acc[mt][nt][2], acc[mt][nt][3]);
                }
        } else if (bn < 2560) {
#pragma unroll
            for (int mt = 0; mt < 4; mt++)
#pragma unroll
                for (int nt = 0; nt < 4; nt++) {
                    int row0 = bm + wm + mt * 16 + grp;
                    int col  = bn - 2048 + wn + nt * 8 + qk * 2;
                    *(float2*)(C2 + (size_t)row0 * 512 + col) =
                        make_float2(acc[mt][nt][0], acc[mt][nt][1]);
                    *(float2*)(C2 + (size_t)(row0 + 8) * 512 + col) =
                        make_float2(acc[mt][nt][2], acc[mt][nt][3]);
                }
        } else {
#pragma unroll
            for (int mt = 0; mt < 4; mt++)
#pragma unroll
                for (int nt = 0; nt < 4; nt++) {
                    int row0 = bm + wm + mt * 16 + grp;
                    int col  = bn - 2560 + wn + nt * 8 + qk * 2;
                    *(__half2*)(C3 + (size_t)row0 * 512 + col) =
                        __floats2half2_rn(acc[mt][nt][0], acc[mt][nt][1]);
                    *(__half2*)(C3 + (size_t)(row0 + 8) * 512 + col) =
                        __floats2half2_rn(acc[mt][nt][2], acc[mt][nt][3]);
                }
        }
    }
}

// ---------------------------------------------------------------------------
// RoPE + QK RMSNorm, z-fused (z=0: Q, z=1: K). fp32 in, fp16 out.
// ---------------------------------------------------------------------------
__global__ __launch_bounds__(128) void rope_norm_kernel(
    const float* __restrict__ qin, __half* __restrict__ qout, const float* __restrict__ qw,
    const float* __restrict__ kin, __half* __restrict__ kout, const float* __restrict__ kw,
    float qscale)
{
    const float* in;
    __half* outh;
    const float* w;
    int nheads;
    float outscale;
    if (blockIdx.z == 0) {
        in = qin; outh = qout; w = qw; nheads = NH_; outscale = qscale;
    } else {
        if (blockIdx.y > 0) return;
        in = kin; outh = kout; w = kw; nheads = NKV_; outscale = 1.0f;
    }

    int tok  = blockIdx.x;
    int warp = threadIdx.x >> 5;
    int lane = threadIdx.x & 31;
    int head = blockIdx.y * 4 + warp;
    int pos  = tok % S_;

    const float* base = in + ((size_t)tok * nheads + head) * HD_;
    float a0 = base[lane];      float a1 = base[lane + 32];
    float b0 = base[lane + 64]; float b1 = base[lane + 96];

    const float* rc = g_rope + (size_t)pos * HD_;
    float c0 = rc[lane],      s0 = rc[64 + lane];
    float c1 = rc[lane + 32], s1 = rc[96 + lane];

    float r0  = a0 * c0 - b0 * s0;
    float r64 = b0 * c0 + a0 * s0;
    float r32 = a1 * c1 - b1 * s1;
    float r96 = b1 * c1 + a1 * s1;

    float ss = r0 * r0 + r32 * r32 + r64 * r64 + r96 * r96;
#pragma unroll
    for (int o = 16; o; o >>= 1) ss += __shfl_xor_sync(0xffffffffu, ss, o);
    float inv = rsqrtf(ss * (1.0f / HD_) + EPSF) * outscale;

    __half* ob = outh + ((size_t)tok * nheads + head) * HD_;
    ob[lane]      = __float2half(w[lane]      * r0  * inv);
    ob[lane + 32] = __float2half(w[lane + 32] * r32 * inv);
    ob[lane + 64] = __float2half(w[lane + 64] * r64 * inv);
    ob[lane + 96] = __float2half(w[lane + 96] * r96 * inv);
}

// ---------------------------------------------------------------------------
// FP16 flash attention, fp16 inputs, ldmatrix feeds.
// ---------------------------------------------------------------------------
#define FBQ 128
#define FBK 64
#define QKW 68
#define VTW 36
#define PW  36
#define QS_WORDS (FBQ * QKW)
#define KS_WORDS (FBK * QKW)
#define VT_WORDS (HD_ * VTW)
#define PS_WORDS (FBQ * PW)
#define FLASH_SMEM ((QS_WORDS + KS_WORDS + VT_WORDS + PS_WORDS) * 4)

__global__ __launch_bounds__(256, 2) void flash_kernel(
    const __half* __restrict__ q, const __half* __restrict__ k,
    const __half* __restrict__ v, __half* __restrict__ o)
{
    extern __shared__ unsigned smw[];
    unsigned* Qw = smw;
    unsigned* Kw = Qw + QS_WORDS;
    unsigned* Vw = Kw + KS_WORDS;
    unsigned* Pw = Vw + VT_WORDS;

    int qb = gridDim.x - 1 - blockIdx.x;
    int bh = blockIdx.y;
    int b  = bh / NH_, h = bh % NH_;
    int kvh = h / (NH_ / NKV_);

    int tid = threadIdx.x;
    int wid = tid >> 5, lane = tid & 31;
    int wm = wid * 16;
    int grp = lane >> 2, qk = lane & 3;

    int mi = lane >> 3, lr = lane & 7;
    int miL = mi & 1, miH = mi >> 1;
    unsigned qAdr, pAdr, kAdr[4], vAdr[8];
    {
        int rowQ = wm + miL * 8 + lr;
        qAdr = smem_u32(Qw) + rowQ * 272 + miH * 16;
        int rowP = wm + miL * 8 + lr;
        pAdr = smem_u32(Pw) + rowP * 144 + miH * 16;
#pragma unroll
        for (int p = 0; p < 4; p++) {
            int rowK = p * 16 + miH * 8 + lr;
            kAdr[p] = smem_u32(Kw) + rowK * 272 + miL * 16;
        }
#pragma unroll
        for (int p = 0; p < 8; p++) {
            int rowV = p * 16 + miH * 8 + lr;
            vAdr[p] = smem_u32(Vw) + rowV * 144 + miL * 16;
        }
    }

    const __half* qbase = q + ((size_t)(b * S_ + qb * FBQ) * NH_ + h) * HD_;
    for (int i = tid; i < FBQ * 16; i += 256) {
        int r  = i >> 4;
        int w4 = (i & 15) * 4;
        uint4 t = *(const uint4*)(qbase + (size_t)r * NH_ * HD_ + w4 * 2);
        unsigned* dst = Qw + r * QKW + w4;
        dst[0] = t.x; dst[1] = t.y; dst[2] = t.z; dst[3] = t.w;
    }

    float m0 = -1e30f, m1 = -1e30f, l0 = 0.f, l1 = 0.f;
    float oacc[16][4];
#pragma unroll
    for (int nt = 0; nt < 16; nt++)
#pragma unroll
        for (int r = 0; r < 4; r++) oacc[nt][r] = 0.f;

    int nkb = 2 * qb + 2;
    for (int kb = 0; kb < nkb; kb++) {
        __syncthreads();
        const __half* kbase = k + ((size_t)(b * S_ + kb * FBK) * NKV_ + kvh) * HD_;
        const __half* vbase = v + ((size_t)(b * S_ + kb * FBK) * NKV_ + kvh) * HD_;
        for (int i = tid; i < FBK * 16; i += 256) {
            int r  = i >> 4;
            int w4 = (i & 15) * 4;
            uint4 t = *(const uint4*)(kbase + (size_t)r * NKV_ * HD_ + w4 * 2);
            unsigned* dst = Kw + r * QKW + w4;
            dst[0] = t.x; dst[1] = t.y; dst[2] = t.z; dst[3] = t.w;
        }
        for (int i = tid; i < 32 * 32; i += 256) {
            int sp = i & 31;
            int c4 = (i >> 5) * 4;
            uint2 va = *(const uint2*)(vbase + (size_t)(2 * sp)     * NKV_ * HD_ + c4);
            uint2 vb = *(const uint2*)(vbase + (size_t)(2 * sp + 1) * NKV_ * HD_ + c4);
            Vw[(c4 + 0) * VTW + sp] = (va.x & 0xFFFFu) | (vb.x << 16);
            Vw[(c4 + 1) * VTW + sp] = (va.x >> 16) | (vb.x & 0xFFFF0000u);
            Vw[(c4 + 2) * VTW + sp] = (va.y & 0xFFFFu) | (vb.y << 16);
            Vw[(c4 + 3) * VTW + sp] = (va.y >> 16) | (vb.y & 0xFFFF0000u);
        }
        __syncthreads();

        float s[8][4];
#pragma unroll
        for (int nt = 0; nt < 8; nt++)
#pragma unroll
            for (int r = 0; r < 4; r++) s[nt][r] = 0.f;

#pragma unroll
        for (int ks = 0; ks < 8; ks++) {
            unsigned koff = ks * 32;
            unsigned a[4];
            ldsm4(a, qAdr + koff);
#pragma unroll
            for (int p = 0; p < 4; p++) {
                unsigned bt[4];
                ldsm4(bt, kAdr[p] + koff);
                mma_f16(s[p * 2],     a, bt);
                mma_f16(s[p * 2 + 1], a, bt + 2);
            }
        }

        if (kb >= 2 * qb) {
            int r0 = qb * FBQ + wm + grp;
            int cb = kb * FBK + qk * 2;
#pragma unroll
            for (int nt = 0; nt < 8; nt++) {
                int c0 = cb + nt * 8;
                if (c0     > r0)     s[nt][0] = -1e30f;
                if (c0 + 1 > r0)     s[nt][1] = -1e30f;
                if (c0     > r0 + 8) s[nt][2] = -1e30f;
                if (c0 + 1 > r0 + 8) s[nt][3] = -1e30f;
            }
        }

        float mx0 = -1e30f, mx1 = -1e30f;
#pragma unroll
        for (int nt = 0; nt < 8; nt++) {
            mx0 = fmaxf(mx0, fmaxf(s[nt][0], s[nt][1]));
            mx1 = fmaxf(mx1, fmaxf(s[nt][2], s[nt][3]));
        }
        mx0 = fmaxf(mx0, __shfl_xor_sync(0xffffffffu, mx0, 1));
        mx0 = fmaxf(mx0, __shfl_xor_sync(0xffffffffu, mx0, 2));
        mx1 = fmaxf(mx1, __shfl_xor_sync(0xffffffffu, mx1, 1));
        mx1 = fmaxf(mx1, __shfl_xor_sync(0xffffffffu, mx1, 2));

        float mn0 = fmaxf(m0, mx0), mn1 = fmaxf(m1, mx1);
        float corr0 = __expf(m0 - mn0), corr1 = __expf(m1 - mn1);
        m0 = mn0; m1 = mn1;

        float rs0 = 0.f, rs1 = 0.f;
#pragma unroll
        for (int nt = 0; nt < 8; nt++) {
            float p0 = __expf(s[nt][0] - mn0);
            float p1 = __expf(s[nt][1] - mn0);
            float p2 = __expf(s[nt][2] - mn1);
            float p3 = __expf(s[nt][3] - mn1);
            rs0 += p0 + p1; rs1 += p2 + p3;
            Pw[(wm + grp)     * PW + nt * 4 + qk] = h2u(__floats2half2_rn(p0, p1));
            Pw[(wm + grp + 8) * PW + nt * 4 + qk] = h2u(__floats2half2_rn(p2, p3));
        }
        rs0 += __shfl_xor_sync(0xffffffffu, rs0, 1);
        rs0 += __shfl_xor_sync(0xffffffffu, rs0, 2);
        rs1 += __shfl_xor_sync(0xffffffffu, rs1, 1);
        rs1 += __shfl_xor_sync(0xffffffffu, rs1, 2);
        l0 = l0 * corr0 + rs0;
        l1 = l1 * corr1 + rs1;

#pragma unroll
        for (int nt = 0; nt < 16; nt++) {
            oacc[nt][0] *= corr0; oacc[nt][1] *= corr0;
            oacc[nt][2] *= corr1; oacc[nt][3] *= corr1;
        }
        __syncwarp();

#pragma unroll
        for (int ks = 0; ks < 4; ks++) {
            unsigned koff = ks * 32;
            unsigned a[4];
            ldsm4(a, pAdr + koff);
#pragma unroll
            for (int p = 0; p < 8; p++) {
                unsigned bt[4];
                ldsm4(bt, vAdr[p] + koff);
                mma_f16(oacc[p * 2],     a, bt);
                mma_f16(oacc[p * 2 + 1], a, bt + 2);
            }
        }
    }

    float inv0 = 1.0f / l0, inv1 = 1.0f / l1;
    int r0 = qb * FBQ + wm + grp;
    __half* out0 = o + ((size_t)(b * S_ + r0) * NH_ + h) * HD_;
    __half* out1 = o + ((size_t)(b * S_ + r0 + 8) * NH_ + h) * HD_;
#pragma unroll
    for (int nt = 0; nt < 16; nt++) {
        int col = nt * 8 + qk * 2;
        *(__half2*)(out0 + col) = __floats2half2_rn(oacc[nt][0] * inv0, oacc[nt][1] * inv0);
        *(__half2*)(out1 + col) = __floats2half2_rn(oacc[nt][2] * inv1, oacc[nt][3] * inv1);
    }
}

// ---------------------------------------------------------------------------
extern "C" void kernel_launch(void* const* d_in, const int* in_sizes, int n_in,
                              void* d_out, int out_size)
{
    const float* hidden = (const float*)d_in[0];
    const float* ln1_w = (const float*)d_in[3];
    const float* Wq    = (const float*)d_in[4];
    const float* Wk    = (const float*)d_in[5];
    const float* Wv    = (const float*)d_in[6];
    const float* Wo    = (const float*)d_in[7];
    const float* qn_w  = (const float*)d_in[8];
    const float* kn_w  = (const float*)d_in[9];
    const float* ln2_w = (const float*)d_in[10];
    const float* Wg    = (const float*)d_in[11];
    const float* Wu    = (const float*)d_in[12];
    const float* Wd    = (const float*)d_in[13];
    float* out = (float*)d_out;

    float *p_q, *p_k, *p_x, *p_g;
    __half *p_qh, *p_kh, *p_vh, *p_hh, *p_oh, *p_gh;
    __half *p_wqkvT, *p_woT, *p_wgT, *p_wuT, *p_wdT;
    cudaGetSymbolAddress((void**)&p_q, g_q);
    cudaGetSymbolAddress((void**)&p_k, g_k);
    cudaGetSymbolAddress((void**)&p_x, g_x);
    cudaGetSymbolAddress((void**)&p_g, g_g);
    cudaGetSymbolAddress((void**)&p_qh, g_qh);
    cudaGetSymbolAddress((void**)&p_kh, g_kh);
    cudaGetSymbolAddress((void**)&p_vh, g_vh);
    cudaGetSymbolAddress((void**)&p_hh, g_hh);
    cudaGetSymbolAddress((void**)&p_oh, g_oh);
    cudaGetSymbolAddress((void**)&p_gh, g_gh);
    cudaGetSymbolAddress((void**)&p_wqkvT, g_wqkvT);
    cudaGetSymbolAddress((void**)&p_woT, g_woT);
    cudaGetSymbolAddress((void**)&p_wgT, g_wgT);
    cudaGetSymbolAddress((void**)&p_wuT, g_wuT);
    cudaGetSymbolAddress((void**)&p_wdT, g_wdT);

    cudaFuncSetAttribute(flash_kernel,
                         cudaFuncAttributeMaxDynamicSharedMemorySize, FLASH_SMEM);
    cudaFuncSetAttribute(gemm_h_kernel,
                         cudaFuncAttributeMaxDynamicSharedMemorySize, HG_SMEM);

    rope_table_kernel<<<(S_ * 64 + 255) / 256, 256>>>();

    dim3 tb(32, 8);
    // Wq into rows [0,2048) of wqkvT; Wk rows [2048,2560); Wv rows [2560,3072)
    transpose_cvt_kernel<<<dim3(64, 64, 1),  tb>>>(Wq, nullptr, p_wqkvT, nullptr, 2048, 2048);
    transpose_cvt_kernel<<<dim3(64, 16, 2),  tb>>>(Wk, Wv,
        p_wqkvT + (size_t)2048 * 2048, p_wqkvT + (size_t)2560 * 2048, 2048, 512);
    transpose_cvt_kernel<<<dim3(64, 64, 1),  tb>>>(Wo, nullptr, p_woT, nullptr, 2048, 2048);
    transpose_cvt_kernel<<<dim3(64, 256, 2), tb>>>(Wg, Wu, p_wgT, p_wuT, 2048, 8192);
    transpose_cvt_kernel<<<dim3(256, 64, 1), tb>>>(Wd, nullptr, p_wdT, nullptr, 8192, 2048);

    // Attention block
    rmsnorm_kernel<<<NTOK, 256>>>(hidden, ln1_w, p_hh);
    gemm_h_kernel<<<dim3(3072 / 128, NTOK / 128, 1), 256, HG_SMEM>>>(
        p_hh, p_wqkvT, nullptr, nullptr, p_q, p_k, p_vh, NTOK, 3072, H_, 3);
    rope_norm_kernel<<<dim3(NTOK, NH_ / 4, 2), 128>>>(
        p_q, p_qh, qn_w, p_k, p_kh, kn_w, 0.08838834764831845f);
    flash_kernel<<<dim3(S_ / FBQ, B_ * NH_), 256, FLASH_SMEM>>>(p_qh, p_kh, p_vh, p_oh);
    gemm_h_kernel<<<dim3(H_ / 128, NTOK / 128, 1), 256, HG_SMEM>>>(
        p_oh, p_woT, nullptr, hidden, p_x, nullptr, nullptr, NTOK, H_, H_, 0);

    // MLP block
    rmsnorm_kernel<<<NTOK, 256>>>(p_x, ln2_w, p_hh);
    gemm_h_kernel<<<dim3(I_ / 128, NTOK / 128, 1), 256, HG_SMEM>>>(
        p_hh, p_wgT, nullptr, nullptr, p_g, nullptr, nullptr, NTOK, I_, H_, 0);
    gemm_h_kernel<<<dim3(I_ / 128, NTOK / 128, 1), 256, HG_SMEM>>>(
        p_hh, p_wuT, nullptr, p_g, (float*)p_gh, nullptr, nullptr, NTOK, I_, H_, 1);
    gemm_h_kernel<<<dim3(H_ / 128, NTOK / 128, 1), 256, HG_SMEM>>>(
        p_gh, p_wdT, nullptr, p_x, out, nullptr, nullptr, NTOK, H_, I_, 0);
}

// round 16
// speedup vs baseline: 1.2118x; 1.0015x over previous
#include <cuda_runtime.h>
#include <cuda_fp16.h>
#include <math.h>
#include <stdint.h>

#define B_   2
#define S_   2048
#define H_   2048
#define NH_  16
#define NKV_ 4
#define HD_  128
#define I_   8192
#define NTOK (B_*S_)
#define EPSF 1e-6f

// ---------------------------------------------------------------------------
__device__ float  g_q [NTOK * NH_ * HD_];
__device__ float  g_k [NTOK * NKV_ * HD_];
__device__ float  g_x [NTOK * H_];
__device__ float  g_g [NTOK * I_];
__device__ float  g_rope[S_ * HD_];
__device__ __half g_qh [NTOK * NH_ * HD_];
__device__ __half g_kh [NTOK * NKV_ * HD_];
__device__ __half g_vh [NTOK * NKV_ * HD_];
__device__ __half g_hh [NTOK * H_];
__device__ __half g_oh [NTOK * NH_ * HD_];
__device__ __half g_gh [NTOK * I_];
__device__ __half g_wqkvT[3072 * 2048];
__device__ __half g_woT[2048 * 2048];
__device__ __half g_wgT[8192 * 2048];
__device__ __half g_wuT[8192 * 2048];
__device__ __half g_wdT[2048 * 8192];

// ---------------------------------------------------------------------------
__device__ __forceinline__ void mma_f16(float* c, const unsigned* a, const unsigned* b) {
    asm volatile(
        "mma.sync.aligned.m16n8k16.row.col.f32.f16.f16.f32 "
        "{%0,%1,%2,%3},{%4,%5,%6,%7},{%8,%9},{%0,%1,%2,%3};\n"
        : "+f"(c[0]), "+f"(c[1]), "+f"(c[2]), "+f"(c[3])
        : "r"(a[0]), "r"(a[1]), "r"(a[2]), "r"(a[3]), "r"(b[0]), "r"(b[1]));
}

__device__ __forceinline__ void ldsm4(unsigned* r, unsigned addr) {
    asm volatile("ldmatrix.sync.aligned.m8n8.x4.shared.b16 {%0,%1,%2,%3}, [%4];"
        : "=r"(r[0]), "=r"(r[1]), "=r"(r[2]), "=r"(r[3]) : "r"(addr));
}

__device__ __forceinline__ unsigned h2u(__half2 h) {
    return *(unsigned*)&h;
}

__device__ __forceinline__ unsigned smem_u32(const void* p) {
    return (unsigned)__cvta_generic_to_shared(p);
}

#define CP_ASYNC16(dst, src) \
    asm volatile("cp.async.ca.shared.global [%0], [%1], 16;" :: "r"(dst), "l"(src))
#define CP_COMMIT() asm volatile("cp.async.commit_group;" ::: "memory")
#define CP_WAIT(n)  asm volatile("cp.async.wait_group %0;" :: "n"(n) : "memory")

// ---------------------------------------------------------------------------
__global__ void rope_table_kernel() {
    int idx = blockIdx.x * blockDim.x + threadIdx.x;
    if (idx >= S_ * 64) return;
    int pos = idx >> 6;
    int i   = idx & 63;
    float invf = 1.0f / powf(10000.0f, (float)i / 64.0f);
    float ang  = (float)pos * invf;
    g_rope[pos * HD_ + i]      = cosf(ang);
    g_rope[pos * HD_ + 64 + i] = sinf(ang);
}

// ---------------------------------------------------------------------------
__global__ __launch_bounds__(256) void transpose_cvt_kernel(
    const float* __restrict__ W, const float* __restrict__ W2,
    __half* __restrict__ Wt, __half* __restrict__ Wt2, int K, int N)
{
    __shared__ float t[32][33];
    if (blockIdx.z == 1) { W = W2; Wt = Wt2; }
    int k0 = blockIdx.x * 32, n0 = blockIdx.y * 32;
    int tx = threadIdx.x, ty = threadIdx.y;
#pragma unroll
    for (int j = ty; j < 32; j += 8)
        t[j][tx] = W[(size_t)(k0 + j) * N + n0 + tx];
    __syncthreads();
    if (tx < 16) {
#pragma unroll
        for (int j = ty; j < 32; j += 8) {
            __half2 hv = __floats2half2_rn(t[2 * tx][j], t[2 * tx + 1][j]);
            *(__half2*)(Wt + (size_t)(n0 + j) * K + k0 + 2 * tx) = hv;
        }
    }
}

// ---------------------------------------------------------------------------
__global__ __launch_bounds__(256) void rmsnorm_kernel(
    const float* __restrict__ x, const float* __restrict__ w,
    __half* __restrict__ out)
{
    int row = blockIdx.x;
    const float* xr = x + (size_t)row * H_;
    float ss = 0.f;
#pragma unroll
    for (int it = 0; it < H_ / (256 * 4); it++) {
        int c = (it * 256 + threadIdx.x) * 4;
        float4 t = *(const float4*)(xr + c);
        ss += t.x * t.x + t.y * t.y + t.z * t.z + t.w * t.w;
    }
#pragma unroll
    for (int o = 16; o; o >>= 1) ss += __shfl_xor_sync(0xffffffffu, ss, o);
    __shared__ float red[8];
    if ((threadIdx.x & 31) == 0) red[threadIdx.x >> 5] = ss;
    __syncthreads();
    float tot = 0.f;
#pragma unroll
    for (int i = 0; i < 8; i++) tot += red[i];
    float inv = rsqrtf(tot * (1.0f / H_) + EPSF);
    __half* orow = out + (size_t)row * H_;
#pragma unroll
    for (int it = 0; it < H_ / (256 * 4); it++) {
        int c = (it * 256 + threadIdx.x) * 4;
        float4 t  = *(const float4*)(xr + c);
        float4 wv = *(const float4*)(w + c);
        __half2 h0 = __floats2half2_rn(wv.x * t.x * inv, wv.y * t.y * inv);
        __half2 h1 = __floats2half2_rn(wv.z * t.z * inv, wv.w * t.w * inv);
        *(__half2*)(orow + c)     = h0;
        *(__half2*)(orow + c + 2) = h1;
    }
}

// ---------------------------------------------------------------------------
// FP16 GEMM (unchanged from R15).
// ---------------------------------------------------------------------------
#define HSTR 72
#define HBUF (128 * HSTR)
#define HG_SMEM (4 * HBUF * 2)

__global__ __launch_bounds__(256, 2) void gemm_h_kernel(
    const __half* __restrict__ A, const __half* __restrict__ Bt,
    const __half* __restrict__ Bt2, const float* __restrict__ addend,
    float* __restrict__ C, float* __restrict__ C2, __half* __restrict__ C3,
    int M, int N, int K, int mode)
{
    extern __shared__ __half smh[];
    __half* As0 = smh;
    __half* Bs0 = smh + HBUF;
    __half* As1 = smh + 2 * HBUF;
    __half* Bs1 = smh + 3 * HBUF;

    if (blockIdx.z == 1) { Bt = Bt2; C = C2; mode >>= 4; }
    mode &= 15;

    int tid = threadIdx.x;
    int bm = blockIdx.y * 128, bn = blockIdx.x * 128;
    int wid = tid >> 5, lane = tid & 31;
    int wm = (wid & 1) * 64;
    int wn = (wid >> 1) * 32;
    int grp = lane >> 2, qk = lane & 3;

    int lrow = tid >> 3;
    int lseg = (tid & 7) * 8;

    const __half* Ag = A  + (size_t)(bm + lrow) * K + lseg;
    const __half* Bg = Bt + (size_t)(bn + lrow) * K + lseg;

    unsigned sa[2], sb[2];
    sa[0] = smem_u32(As0 + lrow * HSTR + lseg);
    sb[0] = smem_u32(Bs0 + lrow * HSTR + lseg);
    sa[1] = smem_u32(As1 + lrow * HSTR + lseg);
    sb[1] = smem_u32(Bs1 + lrow * HSTR + lseg);
    const unsigned rowstep = 32 * HSTR * 2;

    int mi = lane >> 3, lr = lane & 7;
    int miL = mi & 1, miH = mi >> 1;
    unsigned aAdr[2][4], bAdr[2][2];
#pragma unroll
    for (int mt = 0; mt < 4; mt++) {
        int rowA = wm + mt * 16 + miL * 8 + lr;
        aAdr[0][mt] = smem_u32(As0) + rowA * 144 + miH * 16;
        aAdr[1][mt] = smem_u32(As1) + rowA * 144 + miH * 16;
    }
#pragma unroll
    for (int p = 0; p < 2; p++) {
        int rowB = wn + p * 16 + miH * 8 + lr;
        bAdr[0][p] = smem_u32(Bs0) + rowB * 144 + miL * 16;
        bAdr[1][p] = smem_u32(Bs1) + rowB * 144 + miL * 16;
    }

    float acc[4][4][4];
#pragma unroll
    for (int mt = 0; mt < 4; mt++)
#pragma unroll
        for (int nt = 0; nt < 4; nt++)
#pragma unroll
            for (int r = 0; r < 4; r++) acc[mt][nt][r] = 0.f;

    int nk = K / 64;

#pragma unroll
    for (int s = 0; s < 4; s++) {
        CP_ASYNC16(sa[0] + s * rowstep, Ag + (size_t)(32 * s) * K);
        CP_ASYNC16(sb[0] + s * rowstep, Bg + (size_t)(32 * s) * K);
    }
    CP_COMMIT();
    if (nk > 1) {
#pragma unroll
        for (int s = 0; s < 4; s++) {
            CP_ASYNC16(sa[1] + s * rowstep, Ag + (size_t)(32 * s) * K + 64);
            CP_ASYNC16(sb[1] + s * rowstep, Bg + (size_t)(32 * s) * K + 64);
        }
        CP_COMMIT();
        CP_WAIT(1);
    } else {
        CP_WAIT(0);
    }
    __syncthreads();

    for (int kt = 0; kt < nk; kt++) {
        int cur = kt & 1;

#pragma unroll
        for (int ks = 0; ks < 4; ks++) {
            unsigned koff = ks * 32;
            unsigned afr[4][4], bfr[4][2], bt0[4], bt1[4];
#pragma unroll
            for (int mt = 0; mt < 4; mt++)
                ldsm4(afr[mt], aAdr[cur][mt] + koff);
            ldsm4(bt0, bAdr[cur][0] + koff);
            ldsm4(bt1, bAdr[cur][1] + koff);
            bfr[0][0] = bt0[0]; bfr[0][1] = bt0[1];
            bfr[1][0] = bt0[2]; bfr[1][1] = bt0[3];
            bfr[2][0] = bt1[0]; bfr[2][1] = bt1[1];
            bfr[3][0] = bt1[2]; bfr[3][1] = bt1[3];
#pragma unroll
            for (int mt = 0; mt < 4; mt++)
#pragma unroll
                for (int nt = 0; nt < 4; nt++)
                    mma_f16(acc[mt][nt], afr[mt], bfr[nt]);
        }
        __syncthreads();

        if (kt + 2 < nk) {
            const __half* Ag2 = Ag + (size_t)(kt + 2) * 64;
            const __half* Bg2 = Bg + (size_t)(kt + 2) * 64;
#pragma unroll
            for (int s = 0; s < 4; s++) {
                CP_ASYNC16(sa[cur] + s * rowstep, Ag2 + (size_t)(32 * s) * K);
                CP_ASYNC16(sb[cur] + s * rowstep, Bg2 + (size_t)(32 * s) * K);
            }
            CP_COMMIT();
            CP_WAIT(1);
            __syncthreads();
        } else if (kt + 1 < nk) {
            CP_WAIT(0);
            __syncthreads();
        }
    }

    if (mode == 0) {
#pragma unroll
        for (int mt = 0; mt < 4; mt++) {
#pragma unroll
            for (int nt = 0; nt < 4; nt++) {
                int row0 = bm + wm + mt * 16 + grp;
                int col  = bn + wn + nt * 8 + qk * 2;
                float* c0 = C + (size_t)row0 * N + col;
                float* c1 = C + (size_t)(row0 + 8) * N + col;
                if (addend) {
                    const float* a0 = addend + (size_t)row0 * N + col;
                    const float* a1 = addend + (size_t)(row0 + 8) * N + col;
                    *(float2*)c0 = make_float2(acc[mt][nt][0] + a0[0], acc[mt][nt][1] + a0[1]);
                    *(float2*)c1 = make_float2(acc[mt][nt][2] + a1[0], acc[mt][nt][3] + a1[1]);
                } else {
                    *(float2*)c0 = make_float2(acc[mt][nt][0], acc[mt][nt][1]);
                    *(float2*)c1 = make_float2(acc[mt][nt][2], acc[mt][nt][3]);
                }
            }
        }
    } else if (mode == 1) {
        __half* Ch = (__half*)C;
#pragma unroll
        for (int mt = 0; mt < 4; mt++) {
#pragma unroll
            for (int nt = 0; nt < 4; nt++) {
                int row0 = bm + wm + mt * 16 + grp;
                int col  = bn + wn + nt * 8 + qk * 2;
                const float* a0 = addend + (size_t)row0 * N + col;
                const float* a1 = addend + (size_t)(row0 + 8) * N + col;
                float g0 = a0[0], g1 = a0[1], g2 = a1[0], g3 = a1[1];
                float r0 = g0 / (1.f + __expf(-g0)) * acc[mt][nt][0];
                float r1 = g1 / (1.f + __expf(-g1)) * acc[mt][nt][1];
                float r2 = g2 / (1.f + __expf(-g2)) * acc[mt][nt][2];
                float r3 = g3 / (1.f + __expf(-g3)) * acc[mt][nt][3];
                *(__half2*)(Ch + (size_t)row0 * N + col)       = __floats2half2_rn(r0, r1);
                *(__half2*)(Ch + (size_t)(row0 + 8) * N + col) = __floats2half2_rn(r2, r3);
            }
        }
    } else if (mode == 2) {
        __half* Ch = (__half*)C;
#pragma unroll
        for (int mt = 0; mt < 4; mt++) {
#pragma unroll
            for (int nt = 0; nt < 4; nt++) {
                int row0 = bm + wm + mt * 16 + grp;
                int col  = bn + wn + nt * 8 + qk * 2;
                *(__half2*)(Ch + (size_t)row0 * N + col) =
                    __floats2half2_rn(acc[mt][nt][0], acc[mt][nt][1]);
                *(__half2*)(Ch + (size_t)(row0 + 8) * N + col) =
                    __floats2half2_rn(acc[mt][nt][2], acc[mt][nt][3]);
            }
        }
    } else {
        if (bn < 2048) {
#pragma unroll
            for (int mt = 0; mt < 4; mt++)
#pragma unroll
                for (int nt = 0; nt < 4; nt++) {
                    int row0 = bm + wm + mt * 16 + grp;
                    int col  = bn + wn + nt * 8 + qk * 2;
                    *(float2*)(C + (size_t)row0 * 2048 + col) =
                        make_float2(acc[mt][nt][0], acc[mt][nt][1]);
                    *(float2*)(C + (size_t)(row0 + 8) * 2048 + col) =
                        make_float2(acc[mt][nt][2], acc[mt][nt][3]);
                }
        } else if (bn < 2560) {
#pragma unroll
            for (int mt = 0; mt < 4; mt++)
#pragma unroll
                for (int nt = 0; nt < 4; nt++) {
                    int row0 = bm + wm + mt * 16 + grp;
                    int col  = bn - 2048 + wn + nt * 8 + qk * 2;
                    *(float2*)(C2 + (size_t)row0 * 512 + col) =
                        make_float2(acc[mt][nt][0], acc[mt][nt][1]);
                    *(float2*)(C2 + (size_t)(row0 + 8) * 512 + col) =
                        make_float2(acc[mt][nt][2], acc[mt][nt][3]);
                }
        } else {
#pragma unroll
            for (int mt = 0; mt < 4; mt++)
#pragma unroll
                for (int nt = 0; nt < 4; nt++) {
                    int row0 = bm + wm + mt * 16 + grp;
                    int col  = bn - 2560 + wn + nt * 8 + qk * 2;
                    *(__half2*)(C3 + (size_t)row0 * 512 + col) =
                        __floats2half2_rn(acc[mt][nt][0], acc[mt][nt][1]);
                    *(__half2*)(C3 + (size_t)(row0 + 8) * 512 + col) =
                        __floats2half2_rn(acc[mt][nt][2], acc[mt][nt][3]);
                }
        }
    }
}

// ---------------------------------------------------------------------------
__global__ __launch_bounds__(128) void rope_norm_kernel(
    const float* __restrict__ qin, __half* __restrict__ qout, const float* __restrict__ qw,
    const float* __restrict__ kin, __half* __restrict__ kout, const float* __restrict__ kw,
    float qscale)
{
    const float* in;
    __half* outh;
    const float* w;
    int nheads;
    float outscale;
    if (blockIdx.z == 0) {
        in = qin; outh = qout; w = qw; nheads = NH_; outscale = qscale;
    } else {
        if (blockIdx.y > 0) return;
        in = kin; outh = kout; w = kw; nheads = NKV_; outscale = 1.0f;
    }

    int tok  = blockIdx.x;
    int warp = threadIdx.x >> 5;
    int lane = threadIdx.x & 31;
    int head = blockIdx.y * 4 + warp;
    int pos  = tok % S_;

    const float* base = in + ((size_t)tok * nheads + head) * HD_;
    float a0 = base[lane];      float a1 = base[lane + 32];
    float b0 = base[lane + 64]; float b1 = base[lane + 96];

    const float* rc = g_rope + (size_t)pos * HD_;
    float c0 = rc[lane],      s0 = rc[64 + lane];
    float c1 = rc[lane + 32], s1 = rc[96 + lane];

    float r0  = a0 * c0 - b0 * s0;
    float r64 = b0 * c0 + a0 * s0;
    float r32 = a1 * c1 - b1 * s1;
    float r96 = b1 * c1 + a1 * s1;

    float ss = r0 * r0 + r32 * r32 + r64 * r64 + r96 * r96;
#pragma unroll
    for (int o = 16; o; o >>= 1) ss += __shfl_xor_sync(0xffffffffu, ss, o);
    float inv = rsqrtf(ss * (1.0f / HD_) + EPSF) * outscale;

    __half* ob = outh + ((size_t)tok * nheads + head) * HD_;
    ob[lane]      = __float2half(w[lane]      * r0  * inv);
    ob[lane + 32] = __float2half(w[lane + 32] * r32 * inv);
    ob[lane + 64] = __float2half(w[lane + 64] * r64 * inv);
    ob[lane + 96] = __float2half(w[lane + 96] * r96 * inv);
}

// ---------------------------------------------------------------------------
// FP16 flash attention: K double-buffered via cp.async, V register-prefetched.
// Smem: Q + 2*K + V + P = 107.9 KB -> 2 CTAs/SM.
// ---------------------------------------------------------------------------
#define FBQ 128
#define FBK 64
#define QKW 68
#define VTW 36
#define PW  36
#define QS_WORDS (FBQ * QKW)
#define KS_WORDS (FBK * QKW)
#define VT_WORDS (HD_ * VTW)
#define PS_WORDS (FBQ * PW)
#define FLASH_SMEM ((QS_WORDS + 2 * KS_WORDS + VT_WORDS + PS_WORDS) * 4)

__global__ __launch_bounds__(256, 2) void flash_kernel(
    const __half* __restrict__ q, const __half* __restrict__ k,
    const __half* __restrict__ v, __half* __restrict__ o)
{
    extern __shared__ unsigned smw[];
    unsigned* Qw  = smw;
    unsigned* Kw0 = Qw + QS_WORDS;
    unsigned* Kw1 = Kw0 + KS_WORDS;
    unsigned* Vw  = Kw1 + KS_WORDS;
    unsigned* Pw  = Vw + VT_WORDS;

    int qb = gridDim.x - 1 - blockIdx.x;
    int bh = blockIdx.y;
    int b  = bh / NH_, h = bh % NH_;
    int kvh = h / (NH_ / NKV_);

    int tid = threadIdx.x;
    int wid = tid >> 5, lane = tid & 31;
    int wm = wid * 16;
    int grp = lane >> 2, qk = lane & 3;

    int mi = lane >> 3, lr = lane & 7;
    int miL = mi & 1, miH = mi >> 1;
    unsigned qAdr, pAdr, kAdr[2][4], vAdr[8];
    {
        int rowQ = wm + miL * 8 + lr;
        qAdr = smem_u32(Qw) + rowQ * 272 + miH * 16;
        int rowP = wm + miL * 8 + lr;
        pAdr = smem_u32(Pw) + rowP * 144 + miH * 16;
#pragma unroll
        for (int p = 0; p < 4; p++) {
            int rowK = p * 16 + miH * 8 + lr;
            kAdr[0][p] = smem_u32(Kw0) + rowK * 272 + miL * 16;
            kAdr[1][p] = smem_u32(Kw1) + rowK * 272 + miL * 16;
        }
#pragma unroll
        for (int p = 0; p < 8; p++) {
            int rowV = p * 16 + miH * 8 + lr;
            vAdr[p] = smem_u32(Vw) + rowV * 144 + miL * 16;
        }
    }

    // K cp.async per-thread mapping: 4 chunks of 16B (r = tid>>4, w4 = (tid&15)*4)
    int krow = tid >> 4;
    int kw4  = (tid & 15) * 4;
    unsigned kDst[2];
    kDst[0] = smem_u32(Kw0) + (krow * QKW + kw4) * 4;
    kDst[1] = smem_u32(Kw1) + (krow * QKW + kw4) * 4;
    const unsigned kRowStep = 16 * QKW * 4;   // 16 rows in bytes

    // Q tile copy
    const __half* qbase = q + ((size_t)(b * S_ + qb * FBQ) * NH_ + h) * HD_;
    for (int i = tid; i < FBQ * 16; i += 256) {
        int r  = i >> 4;
        int w4 = (i & 15) * 4;
        uint4 t = *(const uint4*)(qbase + (size_t)r * NH_ * HD_ + w4 * 2);
        unsigned* dst = Qw + r * QKW + w4;
        dst[0] = t.x; dst[1] = t.y; dst[2] = t.z; dst[3] = t.w;
    }

    float m0 = -1e30f, m1 = -1e30f, l0 = 0.f, l1 = 0.f;
    float oacc[16][4];
#pragma unroll
    for (int nt = 0; nt < 16; nt++)
#pragma unroll
        for (int r = 0; r < 4; r++) oacc[nt][r] = 0.f;

    int nkb = 2 * qb + 2;
    const __half* kb0 = k + ((size_t)(b * S_) * NKV_ + kvh) * HD_;
    const __half* vb0 = v + ((size_t)(b * S_) * NKV_ + kvh) * HD_;

    // prologue: cp.async K tile 0
    {
        const __half* kbase = kb0 + (size_t)krow * NKV_ * HD_ + kw4 * 2;
#pragma unroll
        for (int s = 0; s < 4; s++)
            CP_ASYNC16(kDst[0] + s * kRowStep, kbase + (size_t)(16 * s) * NKV_ * HD_);
        CP_COMMIT();
    }

    int vsp = tid & 31;          // V load mapping (fixed per thread)
    int vc4 = (tid >> 5) * 4;

    for (int kb = 0; kb < nkb; kb++) {
        int cur = kb & 1;
        __syncthreads();   // previous tile fully consumed (V smem reusable)

        // V register prefetch (independent of K)
        const __half* vbase = vb0 + (size_t)(kb * FBK) * NKV_ * HD_;
        uint2 va[4], vb[4];
#pragma unroll
        for (int s = 0; s < 4; s++) {
            int sp = vsp;
            int c4 = vc4 + s * 32;
            va[s] = *(const uint2*)(vbase + (size_t)(2 * sp)     * NKV_ * HD_ + c4);
            vb[s] = *(const uint2*)(vbase + (size_t)(2 * sp + 1) * NKV_ * HD_ + c4);
        }

        // prefetch next K tile
        if (kb + 1 < nkb) {
            const __half* kbn = kb0 + (size_t)((kb + 1) * FBK + krow) * NKV_ * HD_ + kw4 * 2;
#pragma unroll
            for (int s = 0; s < 4; s++)
                CP_ASYNC16(kDst[cur ^ 1] + s * kRowStep, kbn + (size_t)(16 * s) * NKV_ * HD_);
            CP_COMMIT();
        }

        // V repack into smem
#pragma unroll
        for (int s = 0; s < 4; s++) {
            int sp = vsp;
            int c4 = vc4 + s * 32;
            Vw[(c4 + 0) * VTW + sp] = (va[s].x & 0xFFFFu) | (vb[s].x << 16);
            Vw[(c4 + 1) * VTW + sp] = (va[s].x >> 16) | (vb[s].x & 0xFFFF0000u);
            Vw[(c4 + 2) * VTW + sp] = (va[s].y & 0xFFFFu) | (vb[s].y << 16);
            Vw[(c4 + 3) * VTW + sp] = (va[s].y >> 16) | (vb[s].y & 0xFFFF0000u);
        }

        if (kb + 1 < nkb) { CP_WAIT(1); } else { CP_WAIT(0); }
        __syncthreads();

        float s[8][4];
#pragma unroll
        for (int nt = 0; nt < 8; nt++)
#pragma unroll
            for (int r = 0; r < 4; r++) s[nt][r] = 0.f;

#pragma unroll
        for (int ks = 0; ks < 8; ks++) {
            unsigned koff = ks * 32;
            unsigned a[4];
            ldsm4(a, qAdr + koff);
#pragma unroll
            for (int p = 0; p < 4; p++) {
                unsigned bt[4];
                ldsm4(bt, kAdr[cur][p] + koff);
                mma_f16(s[p * 2],     a, bt);
                mma_f16(s[p * 2 + 1], a, bt + 2);
            }
        }

        if (kb >= 2 * qb) {
            int r0 = qb * FBQ + wm + grp;
            int cb = kb * FBK + qk * 2;
#pragma unroll
            for (int nt = 0; nt < 8; nt++) {
                int c0 = cb + nt * 8;
                if (c0     > r0)     s[nt][0] = -1e30f;
                if (c0 + 1 > r0)     s[nt][1] = -1e30f;
                if (c0     > r0 + 8) s[nt][2] = -1e30f;
                if (c0 + 1 > r0 + 8) s[nt][3] = -1e30f;
            }
        }

        float mx0 = -1e30f, mx1 = -1e30f;
#pragma unroll
        for (int nt = 0; nt < 8; nt++) {
            mx0 = fmaxf(mx0, fmaxf(s[nt][0], s[nt][1]));
            mx1 = fmaxf(mx1, fmaxf(s[nt][2], s[nt][3]));
        }
        mx0 = fmaxf(mx0, __shfl_xor_sync(0xffffffffu, mx0, 1));
        mx0 = fmaxf(mx0, __shfl_xor_sync(0xffffffffu, mx0, 2));
        mx1 = fmaxf(mx1, __shfl_xor_sync(0xffffffffu, mx1, 1));
        mx1 = fmaxf(mx1, __shfl_xor_sync(0xffffffffu, mx1, 2));

        float mn0 = fmaxf(m0, mx0), mn1 = fmaxf(m1, mx1);
        float corr0 = __expf(m0 - mn0), corr1 = __expf(m1 - mn1);
        m0 = mn0; m1 = mn1;

        float rs0 = 0.f, rs1 = 0.f;
#pragma unroll
        for (int nt = 0; nt < 8; nt++) {
            float p0 = __expf(s[nt][0] - mn0);
            float p1 = __expf(s[nt][1] - mn0);
            float p2 = __expf(s[nt][2] - mn1);
            float p3 = __expf(s[nt][3] - mn1);
            rs0 += p0 + p1; rs1 += p2 + p3;
            Pw[(wm + grp)     * PW + nt * 4 + qk] = h2u(__floats2half2_rn(p0, p1));
            Pw[(wm + grp + 8) * PW + nt * 4 + qk] = h2u(__floats2half2_rn(p2, p3));
        }
        rs0 += __shfl_xor_sync(0xffffffffu, rs0, 1);
        rs0 += __shfl_xor_sync(0xffffffffu, rs0, 2);
        rs1 += __shfl_xor_sync(0xffffffffu, rs1, 1);
        rs1 += __shfl_xor_sync(0xffffffffu, rs1, 2);
        l0 = l0 * corr0 + rs0;
        l1 = l1 * corr1 + rs1;

#pragma unroll
        for (int nt = 0; nt < 16; nt++) {
            oacc[nt][0] *= corr0; oacc[nt][1] *= corr0;
            oacc[nt][2] *= corr1; oacc[nt][3] *= corr1;
        }
        __syncwarp();

#pragma unroll
        for (int ks = 0; ks < 4; ks++) {
            unsigned koff = ks * 32;
            unsigned a[4];
            ldsm4(a, pAdr + koff);
#pragma unroll
            for (int p = 0; p < 8; p++) {
                unsigned bt[4];
                ldsm4(bt, vAdr[p] + koff);
                mma_f16(oacc[p * 2],     a, bt);
                mma_f16(oacc[p * 2 + 1], a, bt + 2);
            }
        }
    }

    float inv0 = 1.0f / l0, inv1 = 1.0f / l1;
    int r0 = qb * FBQ + wm + grp;
    __half* out0 = o + ((size_t)(b * S_ + r0) * NH_ + h) * HD_;
    __half* out1 = o + ((size_t)(b * S_ + r0 + 8) * NH_ + h) * HD_;
#pragma unroll
    for (int nt = 0; nt < 16; nt++) {
        int col = nt * 8 + qk * 2;
        *(__half2*)(out0 + col) = __floats2half2_rn(oacc[nt][0] * inv0, oacc[nt][1] * inv0);
        *(__half2*)(out1 + col) = __floats2half2_rn(oacc[nt][2] * inv1, oacc[nt][3] * inv1);
    }
}

// ---------------------------------------------------------------------------
extern "C" void kernel_launch(void* const* d_in, const int* in_sizes, int n_in,
                              void* d_out, int out_size)
{
    const float* hidden = (const float*)d_in[0];
    const float* ln1_w = (const float*)d_in[3];
    const float* Wq    = (const float*)d_in[4];
    const float* Wk    = (const float*)d_in[5];
    const float* Wv    = (const float*)d_in[6];
    const float* Wo    = (const float*)d_in[7];
    const float* qn_w  = (const float*)d_in[8];
    const float* kn_w  = (const float*)d_in[9];
    const float* ln2_w = (const float*)d_in[10];
    const float* Wg    = (const float*)d_in[11];
    const float* Wu    = (const float*)d_in[12];
    const float* Wd    = (const float*)d_in[13];
    float* out = (float*)d_out;

    float *p_q, *p_k, *p_x, *p_g;
    __half *p_qh, *p_kh, *p_vh, *p_hh, *p_oh, *p_gh;
    __half *p_wqkvT, *p_woT, *p_wgT, *p_wuT, *p_wdT;
    cudaGetSymbolAddress((void**)&p_q, g_q);
    cudaGetSymbolAddress((void**)&p_k, g_k);
    cudaGetSymbolAddress((void**)&p_x, g_x);
    cudaGetSymbolAddress((void**)&p_g, g_g);
    cudaGetSymbolAddress((void**)&p_qh, g_qh);
    cudaGetSymbolAddress((void**)&p_kh, g_kh);
    cudaGetSymbolAddress((void**)&p_vh, g_vh);
    cudaGetSymbolAddress((void**)&p_hh, g_hh);
    cudaGetSymbolAddress((void**)&p_oh, g_oh);
    cudaGetSymbolAddress((void**)&p_gh, g_gh);
    cudaGetSymbolAddress((void**)&p_wqkvT, g_wqkvT);
    cudaGetSymbolAddress((void**)&p_woT, g_woT);
    cudaGetSymbolAddress((void**)&p_wgT, g_wgT);
    cudaGetSymbolAddress((void**)&p_wuT, g_wuT);
    cudaGetSymbolAddress((void**)&p_wdT, g_wdT);

    cudaFuncSetAttribute(flash_kernel,
                         cudaFuncAttributeMaxDynamicSharedMemorySize, FLASH_SMEM);
    cudaFuncSetAttribute(gemm_h_kernel,
                         cudaFuncAttributeMaxDynamicSharedMemorySize, HG_SMEM);

    rope_table_kernel<<<(S_ * 64 + 255) / 256, 256>>>();

    dim3 tb(32, 8);
    transpose_cvt_kernel<<<dim3(64, 64, 1),  tb>>>(Wq, nullptr, p_wqkvT, nullptr, 2048, 2048);
    transpose_cvt_kernel<<<dim3(64, 16, 2),  tb>>>(Wk, Wv,
        p_wqkvT + (size_t)2048 * 2048, p_wqkvT + (size_t)2560 * 2048, 2048, 512);
    transpose_cvt_kernel<<<dim3(64, 64, 1),  tb>>>(Wo, nullptr, p_woT, nullptr, 2048, 2048);
    transpose_cvt_kernel<<<dim3(64, 256, 2), tb>>>(Wg, Wu, p_wgT, p_wuT, 2048, 8192);
    transpose_cvt_kernel<<<dim3(256, 64, 1), tb>>>(Wd, nullptr, p_wdT, nullptr, 8192, 2048);

    // Attention block
    rmsnorm_kernel<<<NTOK, 256>>>(hidden, ln1_w, p_hh);
    gemm_h_kernel<<<dim3(3072 / 128, NTOK / 128, 1), 256, HG_SMEM>>>(
        p_hh, p_wqkvT, nullptr, nullptr, p_q, p_k, p_vh, NTOK, 3072, H_, 3);
    rope_norm_kernel<<<dim3(NTOK, NH_ / 4, 2), 128>>>(
        p_q, p_qh, qn_w, p_k, p_kh, kn_w, 0.08838834764831845f);
    flash_kernel<<<dim3(S_ / FBQ, B_ * NH_), 256, FLASH_SMEM>>>(p_qh, p_kh, p_vh, p_oh);
    gemm_h_kernel<<<dim3(H_ / 128, NTOK / 128, 1), 256, HG_SMEM>>>(
        p_oh, p_woT, nullptr, hidden, p_x, nullptr, nullptr, NTOK, H_, H_, 0);

    // MLP block
    rmsnorm_kernel<<<NTOK, 256>>>(p_x, ln2_w, p_hh);
    gemm_h_kernel<<<dim3(I_ / 128, NTOK / 128, 1), 256, HG_SMEM>>>(
        p_hh, p_wgT, nullptr, nullptr, p_g, nullptr, nullptr, NTOK, I_, H_, 0);
    gemm_h_kernel<<<dim3(I_ / 128, NTOK / 128, 1), 256, HG_SMEM>>>(
        p_hh, p_wuT, nullptr, p_g, (float*)p_gh, nullptr, nullptr, NTOK, I_, H_, 1);
    gemm_h_kernel<<<dim3(H_ / 128, NTOK / 128, 1), 256, HG_SMEM>>>(
        p_gh, p_wdT, nullptr, p_x, out, nullptr, nullptr, NTOK, H_, I_, 0);
}

// round 17
// speedup vs baseline: 1.2240x; 1.0100x over previous
#include <cuda_runtime.h>
#include <cuda_fp16.h>
#include <math.h>
#include <stdint.h>

#define B_   2
#define S_   2048
#define H_   2048
#define NH_  16
#define NKV_ 4
#define HD_  128
#define I_   8192
#define NTOK (B_*S_)
#define EPSF 1e-6f

// ---------------------------------------------------------------------------
__device__ float  g_q [NTOK * NH_ * HD_];
__device__ float  g_k [NTOK * NKV_ * HD_];
__device__ float  g_x [NTOK * H_];
__device__ float  g_rope[S_ * HD_];
__device__ __half g_g1 [NTOK * I_];          // gate (fp16)
__device__ __half g_qh [NTOK * NH_ * HD_];
__device__ __half g_kh [NTOK * NKV_ * HD_];
__device__ __half g_vh [NTOK * NKV_ * HD_];
__device__ __half g_hh [NTOK * H_];
__device__ __half g_oh [NTOK * NH_ * HD_];
__device__ __half g_gh [NTOK * I_];
__device__ __half g_wqkvT[3072 * 2048];
__device__ __half g_woT[2048 * 2048];
__device__ __half g_wgT[8192 * 2048];
__device__ __half g_wuT[8192 * 2048];
__device__ __half g_wdT[2048 * 8192];

// ---------------------------------------------------------------------------
__device__ __forceinline__ void mma_f16(float* c, const unsigned* a, const unsigned* b) {
    asm volatile(
        "mma.sync.aligned.m16n8k16.row.col.f32.f16.f16.f32 "
        "{%0,%1,%2,%3},{%4,%5,%6,%7},{%8,%9},{%0,%1,%2,%3};\n"
        : "+f"(c[0]), "+f"(c[1]), "+f"(c[2]), "+f"(c[3])
        : "r"(a[0]), "r"(a[1]), "r"(a[2]), "r"(a[3]), "r"(b[0]), "r"(b[1]));
}

__device__ __forceinline__ void ldsm4(unsigned* r, unsigned addr) {
    asm volatile("ldmatrix.sync.aligned.m8n8.x4.shared.b16 {%0,%1,%2,%3}, [%4];"
        : "=r"(r[0]), "=r"(r[1]), "=r"(r[2]), "=r"(r[3]) : "r"(addr));
}

__device__ __forceinline__ unsigned h2u(__half2 h) {
    return *(unsigned*)&h;
}

__device__ __forceinline__ unsigned smem_u32(const void* p) {
    return (unsigned)__cvta_generic_to_shared(p);
}

#define CP_ASYNC16(dst, src) \
    asm volatile("cp.async.ca.shared.global [%0], [%1], 16;" :: "r"(dst), "l"(src))
#define CP_COMMIT() asm volatile("cp.async.commit_group;" ::: "memory")
#define CP_WAIT(n)  asm volatile("cp.async.wait_group %0;" :: "n"(n) : "memory")

// ---------------------------------------------------------------------------
__global__ void rope_table_kernel() {
    int idx = blockIdx.x * blockDim.x + threadIdx.x;
    if (idx >= S_ * 64) return;
    int pos = idx >> 6;
    int i   = idx & 63;
    float invf = 1.0f / powf(10000.0f, (float)i / 64.0f);
    float ang  = (float)pos * invf;
    g_rope[pos * HD_ + i]      = cosf(ang);
    g_rope[pos * HD_ + 64 + i] = sinf(ang);
}

// ---------------------------------------------------------------------------
__global__ __launch_bounds__(256) void transpose_cvt_kernel(
    const float* __restrict__ W, const float* __restrict__ W2,
    __half* __restrict__ Wt, __half* __restrict__ Wt2, int K, int N)
{
    __shared__ float t[32][33];
    if (blockIdx.z == 1) { W = W2; Wt = Wt2; }
    int k0 = blockIdx.x * 32, n0 = blockIdx.y * 32;
    int tx = threadIdx.x, ty = threadIdx.y;
#pragma unroll
    for (int j = ty; j < 32; j += 8)
        t[j][tx] = W[(size_t)(k0 + j) * N + n0 + tx];
    __syncthreads();
    if (tx < 16) {
#pragma unroll
        for (int j = ty; j < 32; j += 8) {
            __half2 hv = __floats2half2_rn(t[2 * tx][j], t[2 * tx + 1][j]);
            *(__half2*)(Wt + (size_t)(n0 + j) * K + k0 + 2 * tx) = hv;
        }
    }
}

// ---------------------------------------------------------------------------
__global__ __launch_bounds__(256) void rmsnorm_kernel(
    const float* __restrict__ x, const float* __restrict__ w,
    __half* __restrict__ out)
{
    int row = blockIdx.x;
    const float* xr = x + (size_t)row * H_;
    float ss = 0.f;
#pragma unroll
    for (int it = 0; it < H_ / (256 * 4); it++) {
        int c = (it * 256 + threadIdx.x) * 4;
        float4 t = *(const float4*)(xr + c);
        ss += t.x * t.x + t.y * t.y + t.z * t.z + t.w * t.w;
    }
#pragma unroll
    for (int o = 16; o; o >>= 1) ss += __shfl_xor_sync(0xffffffffu, ss, o);
    __shared__ float red[8];
    if ((threadIdx.x & 31) == 0) red[threadIdx.x >> 5] = ss;
    __syncthreads();
    float tot = 0.f;
#pragma unroll
    for (int i = 0; i < 8; i++) tot += red[i];
    float inv = rsqrtf(tot * (1.0f / H_) + EPSF);
    __half* orow = out + (size_t)row * H_;
#pragma unroll
    for (int it = 0; it < H_ / (256 * 4); it++) {
        int c = (it * 256 + threadIdx.x) * 4;
        float4 t  = *(const float4*)(xr + c);
        float4 wv = *(const float4*)(w + c);
        __half2 h0 = __floats2half2_rn(wv.x * t.x * inv, wv.y * t.y * inv);
        __half2 h1 = __floats2half2_rn(wv.z * t.z * inv, wv.w * t.w * inv);
        *(__half2*)(orow + c)     = h0;
        *(__half2*)(orow + c + 2) = h1;
    }
}

// ---------------------------------------------------------------------------
// FP16 GEMM: cp.async 2-stage, ldmatrix, 2 CTAs/SM.
// mode nibble (z-selected): 0 = fp32 C (+opt addend); 1 = silu(f32 addend)->half;
// 2 = plain half C; 3 = QKV routing; 4 = silu(f16 addend)->half.
// ---------------------------------------------------------------------------
#define HSTR 72
#define HBUF (128 * HSTR)
#define HG_SMEM (4 * HBUF * 2)

__global__ __launch_bounds__(256, 2) void gemm_h_kernel(
    const __half* __restrict__ A, const __half* __restrict__ Bt,
    const __half* __restrict__ Bt2, const float* __restrict__ addend,
    float* __restrict__ C, float* __restrict__ C2, __half* __restrict__ C3,
    int M, int N, int K, int mode)
{
    extern __shared__ __half smh[];
    __half* As0 = smh;
    __half* Bs0 = smh + HBUF;
    __half* As1 = smh + 2 * HBUF;
    __half* Bs1 = smh + 3 * HBUF;

    if (blockIdx.z == 1) { Bt = Bt2; C = C2; mode >>= 4; }
    mode &= 15;

    int tid = threadIdx.x;
    int bm = blockIdx.y * 128, bn = blockIdx.x * 128;
    int wid = tid >> 5, lane = tid & 31;
    int wm = (wid & 1) * 64;
    int wn = (wid >> 1) * 32;
    int grp = lane >> 2, qk = lane & 3;

    int lrow = tid >> 3;
    int lseg = (tid & 7) * 8;

    const __half* Ag = A  + (size_t)(bm + lrow) * K + lseg;
    const __half* Bg = Bt + (size_t)(bn + lrow) * K + lseg;

    unsigned sa[2], sb[2];
    sa[0] = smem_u32(As0 + lrow * HSTR + lseg);
    sb[0] = smem_u32(Bs0 + lrow * HSTR + lseg);
    sa[1] = smem_u32(As1 + lrow * HSTR + lseg);
    sb[1] = smem_u32(Bs1 + lrow * HSTR + lseg);
    const unsigned rowstep = 32 * HSTR * 2;

    int mi = lane >> 3, lr = lane & 7;
    int miL = mi & 1, miH = mi >> 1;
    unsigned aAdr[2][4], bAdr[2][2];
#pragma unroll
    for (int mt = 0; mt < 4; mt++) {
        int rowA = wm + mt * 16 + miL * 8 + lr;
        aAdr[0][mt] = smem_u32(As0) + rowA * 144 + miH * 16;
        aAdr[1][mt] = smem_u32(As1) + rowA * 144 + miH * 16;
    }
#pragma unroll
    for (int p = 0; p < 2; p++) {
        int rowB = wn + p * 16 + miH * 8 + lr;
        bAdr[0][p] = smem_u32(Bs0) + rowB * 144 + miL * 16;
        bAdr[1][p] = smem_u32(Bs1) + rowB * 144 + miL * 16;
    }

    float acc[4][4][4];
#pragma unroll
    for (int mt = 0; mt < 4; mt++)
#pragma unroll
        for (int nt = 0; nt < 4; nt++)
#pragma unroll
            for (int r = 0; r < 4; r++) acc[mt][nt][r] = 0.f;

    int nk = K / 64;

#pragma unroll
    for (int s = 0; s < 4; s++) {
        CP_ASYNC16(sa[0] + s * rowstep, Ag + (size_t)(32 * s) * K);
        CP_ASYNC16(sb[0] + s * rowstep, Bg + (size_t)(32 * s) * K);
    }
    CP_COMMIT();
    if (nk > 1) {
#pragma unroll
        for (int s = 0; s < 4; s++) {
            CP_ASYNC16(sa[1] + s * rowstep, Ag + (size_t)(32 * s) * K + 64);
            CP_ASYNC16(sb[1] + s * rowstep, Bg + (size_t)(32 * s) * K + 64);
        }
        CP_COMMIT();
        CP_WAIT(1);
    } else {
        CP_WAIT(0);
    }
    __syncthreads();

    for (int kt = 0; kt < nk; kt++) {
        int cur = kt & 1;

#pragma unroll
        for (int ks = 0; ks < 4; ks++) {
            unsigned koff = ks * 32;
            unsigned afr[4][4], bfr[4][2], bt0[4], bt1[4];
#pragma unroll
            for (int mt = 0; mt < 4; mt++)
                ldsm4(afr[mt], aAdr[cur][mt] + koff);
            ldsm4(bt0, bAdr[cur][0] + koff);
            ldsm4(bt1, bAdr[cur][1] + koff);
            bfr[0][0] = bt0[0]; bfr[0][1] = bt0[1];
            bfr[1][0] = bt0[2]; bfr[1][1] = bt0[3];
            bfr[2][0] = bt1[0]; bfr[2][1] = bt1[1];
            bfr[3][0] = bt1[2]; bfr[3][1] = bt1[3];
#pragma unroll
            for (int mt = 0; mt < 4; mt++)
#pragma unroll
                for (int nt = 0; nt < 4; nt++)
                    mma_f16(acc[mt][nt], afr[mt], bfr[nt]);
        }
        __syncthreads();

        if (kt + 2 < nk) {
            const __half* Ag2 = Ag + (size_t)(kt + 2) * 64;
            const __half* Bg2 = Bg + (size_t)(kt + 2) * 64;
#pragma unroll
            for (int s = 0; s < 4; s++) {
                CP_ASYNC16(sa[cur] + s * rowstep, Ag2 + (size_t)(32 * s) * K);
                CP_ASYNC16(sb[cur] + s * rowstep, Bg2 + (size_t)(32 * s) * K);
            }
            CP_COMMIT();
            CP_WAIT(1);
            __syncthreads();
        } else if (kt + 1 < nk) {
            CP_WAIT(0);
            __syncthreads();
        }
    }

    if (mode == 0) {
#pragma unroll
        for (int mt = 0; mt < 4; mt++) {
#pragma unroll
            for (int nt = 0; nt < 4; nt++) {
                int row0 = bm + wm + mt * 16 + grp;
                int col  = bn + wn + nt * 8 + qk * 2;
                float* c0 = C + (size_t)row0 * N + col;
                float* c1 = C + (size_t)(row0 + 8) * N + col;
                if (addend) {
                    const float* a0 = addend + (size_t)row0 * N + col;
                    const float* a1 = addend + (size_t)(row0 + 8) * N + col;
                    *(float2*)c0 = make_float2(acc[mt][nt][0] + a0[0], acc[mt][nt][1] + a0[1]);
                    *(float2*)c1 = make_float2(acc[mt][nt][2] + a1[0], acc[mt][nt][3] + a1[1]);
                } else {
                    *(float2*)c0 = make_float2(acc[mt][nt][0], acc[mt][nt][1]);
                    *(float2*)c1 = make_float2(acc[mt][nt][2], acc[mt][nt][3]);
                }
            }
        }
    } else if (mode == 4) {
        // silu fusion with fp16 gate: out_h = silu(g_h) * acc
        const __half* ah = (const __half*)addend;
        __half* Ch = (__half*)C;
#pragma unroll
        for (int mt = 0; mt < 4; mt++) {
#pragma unroll
            for (int nt = 0; nt < 4; nt++) {
                int row0 = bm + wm + mt * 16 + grp;
                int col  = bn + wn + nt * 8 + qk * 2;
                __half2 ha = *(const __half2*)(ah + (size_t)row0 * N + col);
                __half2 hb = *(const __half2*)(ah + (size_t)(row0 + 8) * N + col);
                float g0 = __half2float(ha.x), g1 = __half2float(ha.y);
                float g2 = __half2float(hb.x), g3 = __half2float(hb.y);
                float r0 = g0 / (1.f + __expf(-g0)) * acc[mt][nt][0];
                float r1 = g1 / (1.f + __expf(-g1)) * acc[mt][nt][1];
                float r2 = g2 / (1.f + __expf(-g2)) * acc[mt][nt][2];
                float r3 = g3 / (1.f + __expf(-g3)) * acc[mt][nt][3];
                *(__half2*)(Ch + (size_t)row0 * N + col)       = __floats2half2_rn(r0, r1);
                *(__half2*)(Ch + (size_t)(row0 + 8) * N + col) = __floats2half2_rn(r2, r3);
            }
        }
    } else if (mode == 2) {
        __half* Ch = (__half*)C;
#pragma unroll
        for (int mt = 0; mt < 4; mt++) {
#pragma unroll
            for (int nt = 0; nt < 4; nt++) {
                int row0 = bm + wm + mt * 16 + grp;
                int col  = bn + wn + nt * 8 + qk * 2;
                *(__half2*)(Ch + (size_t)row0 * N + col) =
                    __floats2half2_rn(acc[mt][nt][0], acc[mt][nt][1]);
                *(__half2*)(Ch + (size_t)(row0 + 8) * N + col) =
                    __floats2half2_rn(acc[mt][nt][2], acc[mt][nt][3]);
            }
        }
    } else {
        if (bn < 2048) {
#pragma unroll
            for (int mt = 0; mt < 4; mt++)
#pragma unroll
                for (int nt = 0; nt < 4; nt++) {
                    int row0 = bm + wm + mt * 16 + grp;
                    int col  = bn + wn + nt * 8 + qk * 2;
                    *(float2*)(C + (size_t)row0 * 2048 + col) =
                        make_float2(acc[mt][nt][0], acc[mt][nt][1]);
                    *(float2*)(C + (size_t)(row0 + 8) * 2048 + col) =
                        make_float2(acc[mt][nt][2], acc[mt][nt][3]);
                }
        } else if (bn < 2560) {
#pragma unroll
            for (int mt = 0; mt < 4; mt++)
#pragma unroll
                for (int nt = 0; nt < 4; nt++) {
                    int row0 = bm + wm + mt * 16 + grp;
                    int col  = bn - 2048 + wn + nt * 8 + qk * 2;
                    *(float2*)(C2 + (size_t)row0 * 512 + col) =
                        make_float2(acc[mt][nt][0], acc[mt][nt][1]);
                    *(float2*)(C2 + (size_t)(row0 + 8) * 512 + col) =
                        make_float2(acc[mt][nt][2], acc[mt][nt][3]);
                }
        } else {
#pragma unroll
            for (int mt = 0; mt < 4; mt++)
#pragma unroll
                for (int nt = 0; nt < 4; nt++) {
                    int row0 = bm + wm + mt * 16 + grp;
                    int col  = bn - 2560 + wn + nt * 8 + qk * 2;
                    *(__half2*)(C3 + (size_t)row0 * 512 + col) =
                        __floats2half2_rn(acc[mt][nt][0], acc[mt][nt][1]);
                    *(__half2*)(C3 + (size_t)(row0 + 8) * 512 + col) =
                        __floats2half2_rn(acc[mt][nt][2], acc[mt][nt][3]);
                }
        }
    }
}

// ---------------------------------------------------------------------------
__global__ __launch_bounds__(128) void rope_norm_kernel(
    const float* __restrict__ qin, __half* __restrict__ qout, const float* __restrict__ qw,
    const float* __restrict__ kin, __half* __restrict__ kout, const float* __restrict__ kw,
    float qscale)
{
    const float* in;
    __half* outh;
    const float* w;
    int nheads;
    float outscale;
    if (blockIdx.z == 0) {
        in = qin; outh = qout; w = qw; nheads = NH_; outscale = qscale;
    } else {
        if (blockIdx.y > 0) return;
        in = kin; outh = kout; w = kw; nheads = NKV_; outscale = 1.0f;
    }

    int tok  = blockIdx.x;
    int warp = threadIdx.x >> 5;
    int lane = threadIdx.x & 31;
    int head = blockIdx.y * 4 + warp;
    int pos  = tok % S_;

    const float* base = in + ((size_t)tok * nheads + head) * HD_;
    float a0 = base[lane];      float a1 = base[lane + 32];
    float b0 = base[lane + 64]; float b1 = base[lane + 96];

    const float* rc = g_rope + (size_t)pos * HD_;
    float c0 = rc[lane],      s0 = rc[64 + lane];
    float c1 = rc[lane + 32], s1 = rc[96 + lane];

    float r0  = a0 * c0 - b0 * s0;
    float r64 = b0 * c0 + a0 * s0;
    float r32 = a1 * c1 - b1 * s1;
    float r96 = b1 * c1 + a1 * s1;

    float ss = r0 * r0 + r32 * r32 + r64 * r64 + r96 * r96;
#pragma unroll
    for (int o = 16; o; o >>= 1) ss += __shfl_xor_sync(0xffffffffu, ss, o);
    float inv = rsqrtf(ss * (1.0f / HD_) + EPSF) * outscale;

    __half* ob = outh + ((size_t)tok * nheads + head) * HD_;
    ob[lane]      = __float2half(w[lane]      * r0  * inv);
    ob[lane + 32] = __float2half(w[lane + 32] * r32 * inv);
    ob[lane + 64] = __float2half(w[lane + 64] * r64 * inv);
    ob[lane + 96] = __float2half(w[lane + 96] * r96 * inv);
}

// ---------------------------------------------------------------------------
// FP16 flash attention (R16 structure: K cp.async double-buffer, V reg prefetch)
// ---------------------------------------------------------------------------
#define FBQ 128
#define FBK 64
#define QKW 68
#define VTW 36
#define PW  36
#define QS_WORDS (FBQ * QKW)
#define KS_WORDS (FBK * QKW)
#define VT_WORDS (HD_ * VTW)
#define PS_WORDS (FBQ * PW)
#define FLASH_SMEM ((QS_WORDS + 2 * KS_WORDS + VT_WORDS + PS_WORDS) * 4)

__global__ __launch_bounds__(256, 2) void flash_kernel(
    const __half* __restrict__ q, const __half* __restrict__ k,
    const __half* __restrict__ v, __half* __restrict__ o)
{
    extern __shared__ unsigned smw[];
    unsigned* Qw  = smw;
    unsigned* Kw0 = Qw + QS_WORDS;
    unsigned* Kw1 = Kw0 + KS_WORDS;
    unsigned* Vw  = Kw1 + KS_WORDS;
    unsigned* Pw  = Vw + VT_WORDS;

    int qb = gridDim.x - 1 - blockIdx.x;
    int bh = blockIdx.y;
    int b  = bh / NH_, h = bh % NH_;
    int kvh = h / (NH_ / NKV_);

    int tid = threadIdx.x;
    int wid = tid >> 5, lane = tid & 31;
    int wm = wid * 16;
    int grp = lane >> 2, qk = lane & 3;

    int mi = lane >> 3, lr = lane & 7;
    int miL = mi & 1, miH = mi >> 1;
    unsigned qAdr, pAdr, kAdr[2][4], vAdr[8];
    {
        int rowQ = wm + miL * 8 + lr;
        qAdr = smem_u32(Qw) + rowQ * 272 + miH * 16;
        int rowP = wm + miL * 8 + lr;
        pAdr = smem_u32(Pw) + rowP * 144 + miH * 16;
#pragma unroll
        for (int p = 0; p < 4; p++) {
            int rowK = p * 16 + miH * 8 + lr;
            kAdr[0][p] = smem_u32(Kw0) + rowK * 272 + miL * 16;
            kAdr[1][p] = smem_u32(Kw1) + rowK * 272 + miL * 16;
        }
#pragma unroll
        for (int p = 0; p < 8; p++) {
            int rowV = p * 16 + miH * 8 + lr;
            vAdr[p] = smem_u32(Vw) + rowV * 144 + miL * 16;
        }
    }

    int krow = tid >> 4;
    int kw4  = (tid & 15) * 4;
    unsigned kDst[2];
    kDst[0] = smem_u32(Kw0) + (krow * QKW + kw4) * 4;
    kDst[1] = smem_u32(Kw1) + (krow * QKW + kw4) * 4;
    const unsigned kRowStep = 16 * QKW * 4;

    const __half* qbase = q + ((size_t)(b * S_ + qb * FBQ) * NH_ + h) * HD_;
    for (int i = tid; i < FBQ * 16; i += 256) {
        int r  = i >> 4;
        int w4 = (i & 15) * 4;
        uint4 t = *(const uint4*)(qbase + (size_t)r * NH_ * HD_ + w4 * 2);
        unsigned* dst = Qw + r * QKW + w4;
        dst[0] = t.x; dst[1] = t.y; dst[2] = t.z; dst[3] = t.w;
    }

    float m0 = -1e30f, m1 = -1e30f, l0 = 0.f, l1 = 0.f;
    float oacc[16][4];
#pragma unroll
    for (int nt = 0; nt < 16; nt++)
#pragma unroll
        for (int r = 0; r < 4; r++) oacc[nt][r] = 0.f;

    int nkb = 2 * qb + 2;
    const __half* kb0 = k + ((size_t)(b * S_) * NKV_ + kvh) * HD_;
    const __half* vb0 = v + ((size_t)(b * S_) * NKV_ + kvh) * HD_;

    {
        const __half* kbase = kb0 + (size_t)krow * NKV_ * HD_ + kw4 * 2;
#pragma unroll
        for (int s = 0; s < 4; s++)
            CP_ASYNC16(kDst[0] + s * kRowStep, kbase + (size_t)(16 * s) * NKV_ * HD_);
        CP_COMMIT();
    }

    int vsp = tid & 31;
    int vc4 = (tid >> 5) * 4;

    for (int kb = 0; kb < nkb; kb++) {
        int cur = kb & 1;
        __syncthreads();

        const __half* vbase = vb0 + (size_t)(kb * FBK) * NKV_ * HD_;
        uint2 va[4], vb[4];
#pragma unroll
        for (int s = 0; s < 4; s++) {
            int sp = vsp;
            int c4 = vc4 + s * 32;
            va[s] = *(const uint2*)(vbase + (size_t)(2 * sp)     * NKV_ * HD_ + c4);
            vb[s] = *(const uint2*)(vbase + (size_t)(2 * sp + 1) * NKV_ * HD_ + c4);
        }

        if (kb + 1 < nkb) {
            const __half* kbn = kb0 + (size_t)((kb + 1) * FBK + krow) * NKV_ * HD_ + kw4 * 2;
#pragma unroll
            for (int s = 0; s < 4; s++)
                CP_ASYNC16(kDst[cur ^ 1] + s * kRowStep, kbn + (size_t)(16 * s) * NKV_ * HD_);
            CP_COMMIT();
        }

#pragma unroll
        for (int s = 0; s < 4; s++) {
            int sp = vsp;
            int c4 = vc4 + s * 32;
            Vw[(c4 + 0) * VTW + sp] = (va[s].x & 0xFFFFu) | (vb[s].x << 16);
            Vw[(c4 + 1) * VTW + sp] = (va[s].x >> 16) | (vb[s].x & 0xFFFF0000u);
            Vw[(c4 + 2) * VTW + sp] = (va[s].y & 0xFFFFu) | (vb[s].y << 16);
            Vw[(c4 + 3) * VTW + sp] = (va[s].y >> 16) | (vb[s].y & 0xFFFF0000u);
        }

        if (kb + 1 < nkb) { CP_WAIT(1); } else { CP_WAIT(0); }
        __syncthreads();

        float s[8][4];
#pragma unroll
        for (int nt = 0; nt < 8; nt++)
#pragma unroll
            for (int r = 0; r < 4; r++) s[nt][r] = 0.f;

#pragma unroll
        for (int ks = 0; ks < 8; ks++) {
            unsigned koff = ks * 32;
            unsigned a[4];
            ldsm4(a, qAdr + koff);
#pragma unroll
            for (int p = 0; p < 4; p++) {
                unsigned bt[4];
                ldsm4(bt, kAdr[cur][p] + koff);
                mma_f16(s[p * 2],     a, bt);
                mma_f16(s[p * 2 + 1], a, bt + 2);
            }
        }

        if (kb >= 2 * qb) {
            int r0 = qb * FBQ + wm + grp;
            int cb = kb * FBK + qk * 2;
#pragma unroll
            for (int nt = 0; nt < 8; nt++) {
                int c0 = cb + nt * 8;
                if (c0     > r0)     s[nt][0] = -1e30f;
                if (c0 + 1 > r0)     s[nt][1] = -1e30f;
                if (c0     > r0 + 8) s[nt][2] = -1e30f;
                if (c0 + 1 > r0 + 8) s[nt][3] = -1e30f;
            }
        }

        float mx0 = -1e30f, mx1 = -1e30f;
#pragma unroll
        for (int nt = 0; nt < 8; nt++) {
            mx0 = fmaxf(mx0, fmaxf(s[nt][0], s[nt][1]));
            mx1 = fmaxf(mx1, fmaxf(s[nt][2], s[nt][3]));
        }
        mx0 = fmaxf(mx0, __shfl_xor_sync(0xffffffffu, mx0, 1));
        mx0 = fmaxf(mx0, __shfl_xor_sync(0xffffffffu, mx0, 2));
        mx1 = fmaxf(mx1, __shfl_xor_sync(0xffffffffu, mx1, 1));
        mx1 = fmaxf(mx1, __shfl_xor_sync(0xffffffffu, mx1, 2));

        float mn0 = fmaxf(m0, mx0), mn1 = fmaxf(m1, mx1);
        float corr0 = __expf(m0 - mn0), corr1 = __expf(m1 - mn1);
        m0 = mn0; m1 = mn1;

        float rs0 = 0.f, rs1 = 0.f;
#pragma unroll
        for (int nt = 0; nt < 8; nt++) {
            float p0 = __expf(s[nt][0] - mn0);
            float p1 = __expf(s[nt][1] - mn0);
            float p2 = __expf(s[nt][2] - mn1);
            float p3 = __expf(s[nt][3] - mn1);
            rs0 += p0 + p1; rs1 += p2 + p3;
            Pw[(wm + grp)     * PW + nt * 4 + qk] = h2u(__floats2half2_rn(p0, p1));
            Pw[(wm + grp + 8) * PW + nt * 4 + qk] = h2u(__floats2half2_rn(p2, p3));
        }
        rs0 += __shfl_xor_sync(0xffffffffu, rs0, 1);
        rs0 += __shfl_xor_sync(0xffffffffu, rs0, 2);
        rs1 += __shfl_xor_sync(0xffffffffu, rs1, 1);
        rs1 += __shfl_xor_sync(0xffffffffu, rs1, 2);
        l0 = l0 * corr0 + rs0;
        l1 = l1 * corr1 + rs1;

#pragma unroll
        for (int nt = 0; nt < 16; nt++) {
            oacc[nt][0] *= corr0; oacc[nt][1] *= corr0;
            oacc[nt][2] *= corr1; oacc[nt][3] *= corr1;
        }
        __syncwarp();

#pragma unroll
        for (int ks = 0; ks < 4; ks++) {
            unsigned koff = ks * 32;
            unsigned a[4];
            ldsm4(a, pAdr + koff);
#pragma unroll
            for (int p = 0; p < 8; p++) {
                unsigned bt[4];
                ldsm4(bt, vAdr[p] + koff);
                mma_f16(oacc[p * 2],     a, bt);
                mma_f16(oacc[p * 2 + 1], a, bt + 2);
            }
        }
    }

    float inv0 = 1.0f / l0, inv1 = 1.0f / l1;
    int r0 = qb * FBQ + wm + grp;
    __half* out0 = o + ((size_t)(b * S_ + r0) * NH_ + h) * HD_;
    __half* out1 = o + ((size_t)(b * S_ + r0 + 8) * NH_ + h) * HD_;
#pragma unroll
    for (int nt = 0; nt < 16; nt++) {
        int col = nt * 8 + qk * 2;
        *(__half2*)(out0 + col) = __floats2half2_rn(oacc[nt][0] * inv0, oacc[nt][1] * inv0);
        *(__half2*)(out1 + col) = __floats2half2_rn(oacc[nt][2] * inv1, oacc[nt][3] * inv1);
    }
}

// ---------------------------------------------------------------------------
extern "C" void kernel_launch(void* const* d_in, const int* in_sizes, int n_in,
                              void* d_out, int out_size)
{
    const float* hidden = (const float*)d_in[0];
    const float* ln1_w = (const float*)d_in[3];
    const float* Wq    = (const float*)d_in[4];
    const float* Wk    = (const float*)d_in[5];
    const float* Wv    = (const float*)d_in[6];
    const float* Wo    = (const float*)d_in[7];
    const float* qn_w  = (const float*)d_in[8];
    const float* kn_w  = (const float*)d_in[9];
    const float* ln2_w = (const float*)d_in[10];
    const float* Wg    = (const float*)d_in[11];
    const float* Wu    = (const float*)d_in[12];
    const float* Wd    = (const float*)d_in[13];
    float* out = (float*)d_out;

    float *p_q, *p_k, *p_x;
    __half *p_g1, *p_qh, *p_kh, *p_vh, *p_hh, *p_oh, *p_gh;
    __half *p_wqkvT, *p_woT, *p_wgT, *p_wuT, *p_wdT;
    cudaGetSymbolAddress((void**)&p_q, g_q);
    cudaGetSymbolAddress((void**)&p_k, g_k);
    cudaGetSymbolAddress((void**)&p_x, g_x);
    cudaGetSymbolAddress((void**)&p_g1, g_g1);
    cudaGetSymbolAddress((void**)&p_qh, g_qh);
    cudaGetSymbolAddress((void**)&p_kh, g_kh);
    cudaGetSymbolAddress((void**)&p_vh, g_vh);
    cudaGetSymbolAddress((void**)&p_hh, g_hh);
    cudaGetSymbolAddress((void**)&p_oh, g_oh);
    cudaGetSymbolAddress((void**)&p_gh, g_gh);
    cudaGetSymbolAddress((void**)&p_wqkvT, g_wqkvT);
    cudaGetSymbolAddress((void**)&p_woT, g_woT);
    cudaGetSymbolAddress((void**)&p_wgT, g_wgT);
    cudaGetSymbolAddress((void**)&p_wuT, g_wuT);
    cudaGetSymbolAddress((void**)&p_wdT, g_wdT);

    cudaFuncSetAttribute(flash_kernel,
                         cudaFuncAttributeMaxDynamicSharedMemorySize, FLASH_SMEM);
    cudaFuncSetAttribute(gemm_h_kernel,
                         cudaFuncAttributeMaxDynamicSharedMemorySize, HG_SMEM);

    rope_table_kernel<<<(S_ * 64 + 255) / 256, 256>>>();

    dim3 tb(32, 8);
    // z-fused: Wq (z=0) + Wo (z=1); Wk+Wv; Wg+Wu; Wd alone
    transpose_cvt_kernel<<<dim3(64, 64, 2),  tb>>>(Wq, Wo, p_wqkvT, p_woT, 2048, 2048);
    transpose_cvt_kernel<<<dim3(64, 16, 2),  tb>>>(Wk, Wv,
        p_wqkvT + (size_t)2048 * 2048, p_wqkvT + (size_t)2560 * 2048, 2048, 512);
    transpose_cvt_kernel<<<dim3(64, 256, 2), tb>>>(Wg, Wu, p_wgT, p_wuT, 2048, 8192);
    transpose_cvt_kernel<<<dim3(256, 64, 1), tb>>>(Wd, nullptr, p_wdT, nullptr, 8192, 2048);

    // Attention block
    rmsnorm_kernel<<<NTOK, 256>>>(hidden, ln1_w, p_hh);
    gemm_h_kernel<<<dim3(3072 / 128, NTOK / 128, 1), 256, HG_SMEM>>>(
        p_hh, p_wqkvT, nullptr, nullptr, p_q, p_k, p_vh, NTOK, 3072, H_, 3);
    rope_norm_kernel<<<dim3(NTOK, NH_ / 4, 2), 128>>>(
        p_q, p_qh, qn_w, p_k, p_kh, kn_w, 0.08838834764831845f);
    flash_kernel<<<dim3(S_ / FBQ, B_ * NH_), 256, FLASH_SMEM>>>(p_qh, p_kh, p_vh, p_oh);
    gemm_h_kernel<<<dim3(H_ / 128, NTOK / 128, 1), 256, HG_SMEM>>>(
        p_oh, p_woT, nullptr, hidden, p_x, nullptr, nullptr, NTOK, H_, H_, 0);

    // MLP block
    rmsnorm_kernel<<<NTOK, 256>>>(p_x, ln2_w, p_hh);
    gemm_h_kernel<<<dim3(I_ / 128, NTOK / 128, 1), 256, HG_SMEM>>>(
        p_hh, p_wgT, nullptr, nullptr, (float*)p_g1, nullptr, nullptr, NTOK, I_, H_, 2);
    gemm_h_kernel<<<dim3(I_ / 128, NTOK / 128, 1), 256, HG_SMEM>>>(
        p_hh, p_wuT, nullptr, (const float*)p_g1, (float*)p_gh, nullptr, nullptr, NTOK, I_, H_, 4);
    gemm_h_kernel<<<dim3(H_ / 128, NTOK / 128, 1), 256, HG_SMEM>>>(
        p_gh, p_wdT, nullptr, p_x, out, nullptr, nullptr, NTOK, H_, I_, 0);
}